// round 1
// baseline (speedup 1.0000x reference)
#include <cuda_runtime.h>
#include <math.h>

#define NB 8
#define NT 1024
#define NC 1024
#define NH 16
#define NM (NB*NT)

// ---------------- scratch (static device globals, no allocation) -------------
__device__ float g_xs  [NM*NC];
__device__ float g_k   [NM*NC];
__device__ float g_v   [NM*NC];
__device__ float g_r   [NM*NC];
__device__ float g_sumk[NM*NC];
__device__ float g_wkv [NM*NC];
__device__ float g_rwkv[NM*NC];
__device__ float g_WT  [4][NC*NC];   // WkT, WvT, WrT, WoT  ([K,N] layouts)

// ---------------- transpose: W[N,K] -> Wt[K,N] -------------------------------
__global__ void transpose_kernel(const float* __restrict__ src,
                                 float* __restrict__ dst) {
    __shared__ float tile[32][33];
    int x0 = blockIdx.x * 32, y0 = blockIdx.y * 32;
#pragma unroll
    for (int j = 0; j < 32; j += 8)
        tile[threadIdx.y + j][threadIdx.x] =
            src[(y0 + threadIdx.y + j) * NC + x0 + threadIdx.x];
    __syncthreads();
#pragma unroll
    for (int j = 0; j < 32; j += 8)
        dst[(x0 + threadIdx.y + j) * NC + y0 + threadIdx.x] =
            tile[threadIdx.x][threadIdx.y + j];
}

// ---------------- time-shift ---------------------------------------------------
__global__ void build_xs_kernel(const float* __restrict__ x) {
    int i = blockIdx.x * 256 + threadIdx.x;      // over NM*NC
    int c = i & (NC - 1);
    int t = (i / NC) & (NT - 1);
    float val;
    if (c < NC / 2)
        val = (t == 0) ? 0.f : x[i - NC];
    else
        val = x[i];
    g_xs[i] = val;
}

// ---------------- 128x128x8 fp32 GEMM:  C = A[M,K] * Bt[K,N] + bias ----------
// EPI: 0 = plain, 1 = exp(clip(.,-60,30)) (k path), 2 = *gamma[t] (output path)
template<int EPI>
__global__ void __launch_bounds__(256, 2) gemm_kernel(
    const float* __restrict__ A, const float* __restrict__ Bt,
    float* __restrict__ C, const float* __restrict__ bias,
    const float* __restrict__ gamma)
{
    __shared__ float As[8][128];
    __shared__ float Bs[8][132];

    int tid = threadIdx.x;
    int m0 = blockIdx.x * 128, n0 = blockIdx.y * 128;
    int am = tid >> 1, ak = (tid & 1) * 4;
    int bk = tid >> 5, bn = (tid & 31) * 4;
    const float* Ap = A + (size_t)(m0 + am) * NC + ak;
    const float* Bp = Bt + (size_t)bk * NC + n0 + bn;
    int ty = tid >> 4, tx = tid & 15;

    float acc[8][8];
#pragma unroll
    for (int i = 0; i < 8; i++)
#pragma unroll
        for (int j = 0; j < 8; j++) acc[i][j] = 0.f;

    for (int k0 = 0; k0 < NC; k0 += 8) {
        float4 a4 = *(const float4*)Ap;
        float4 b4 = *(const float4*)Bp;
        __syncthreads();
        As[ak + 0][am] = a4.x; As[ak + 1][am] = a4.y;
        As[ak + 2][am] = a4.z; As[ak + 3][am] = a4.w;
        *(float4*)&Bs[bk][bn] = b4;
        __syncthreads();
#pragma unroll
        for (int kk = 0; kk < 8; kk++) {
            float4 a0 = *(const float4*)&As[kk][ty * 8];
            float4 a1 = *(const float4*)&As[kk][ty * 8 + 4];
            float4 b0 = *(const float4*)&Bs[kk][tx * 8];
            float4 b1 = *(const float4*)&Bs[kk][tx * 8 + 4];
            float ar[8] = {a0.x, a0.y, a0.z, a0.w, a1.x, a1.y, a1.z, a1.w};
            float br[8] = {b0.x, b0.y, b0.z, b0.w, b1.x, b1.y, b1.z, b1.w};
#pragma unroll
            for (int i = 0; i < 8; i++)
#pragma unroll
                for (int j = 0; j < 8; j++)
                    acc[i][j] += ar[i] * br[j];
        }
        Ap += 8;
        Bp += 8 * NC;
    }

#pragma unroll
    for (int i = 0; i < 8; i++) {
        int m = m0 + ty * 8 + i;
        float g = 1.f;
        if (EPI == 2) g = gamma[m & (NT - 1)];
#pragma unroll
        for (int jj = 0; jj < 8; jj += 4) {
            float4 o;
            float* op = &o.x;
#pragma unroll
            for (int j = 0; j < 4; j++) {
                int n = n0 + tx * 8 + jj + j;
                float val = acc[i][jj + j] + bias[n];
                if (EPI == 1) val = expf(fminf(fmaxf(val, -60.f), 30.f));
                if (EPI == 2) val *= g;
                op[j] = val;
            }
            *(float4*)&C[(size_t)m * NC + n0 + tx * 8 + jj] = o;
        }
    }
}

// ---------------- cumsum over t (per (b,channel)) ----------------------------
__global__ void cumsum_kernel() {
    int c = blockIdx.x * 256 + threadIdx.x;
    int b = blockIdx.y;
    const float* src = g_k    + (size_t)b * NT * NC + c;
    float*       dst = g_sumk + (size_t)b * NT * NC + c;
    float s = 0.f;
    for (int t0 = 0; t0 < NT; t0 += 16) {
        float buf[16];
#pragma unroll
        for (int j = 0; j < 16; j++) buf[j] = src[(size_t)(t0 + j) * NC];
#pragma unroll
        for (int j = 0; j < 16; j++) { s += buf[j]; dst[(size_t)(t0 + j) * NC] = s; }
    }
}

// ---------------- wkv: causal per-head decay matmul --------------------------
// wkv[b,t,h,c] = beta[h,t] * sum_{u<=t} time_w[h,1023-t+u] * alpha[h,u] * k*v[b,u,h,c]
__global__ void __launch_bounds__(256) wkv_kernel(
    const float* __restrict__ time_w, const float* __restrict__ alpha,
    const float* __restrict__ beta)
{
    __shared__ float tw[NT];
    __shared__ float ws [64][68];   // [uu][ti]
    __shared__ float kvs[64][68];   // [uu][c]

    int tt = blockIdx.x;                 // t tile (0..15)
    int b = blockIdx.y >> 4, h = blockIdx.y & 15;
    int tid = threadIdx.x;

    for (int i = tid; i < NT; i += 256) tw[i] = time_w[h * NT + i];

    int t0 = tt * 64;
    int ty = tid >> 4, tx = tid & 15;
    float acc[4][4];
#pragma unroll
    for (int i = 0; i < 4; i++)
#pragma unroll
        for (int j = 0; j < 4; j++) acc[i][j] = 0.f;

    const float* kbase = g_k + (size_t)b * NT * NC + h * 64;
    const float* vbase = g_v + (size_t)b * NT * NC + h * 64;

    for (int ut = 0; ut <= tt; ut++) {
        int u0 = ut * 64;
        __syncthreads();
#pragma unroll 4
        for (int r = 0; r < 16; r++) {
            int i = tid + r * 256;
            int uu = i >> 6, cc = i & 63;
            int u = u0 + uu;
            kvs[uu][cc] = kbase[(size_t)u * NC + cc] * vbase[(size_t)u * NC + cc]
                        * alpha[h * NT + u];
            int t = t0 + cc;             // cc doubles as ti for ws fill
            float wv = 0.f;
            if (u <= t) wv = tw[1023 - t + u];
            ws[uu][cc] = wv;
        }
        __syncthreads();
#pragma unroll
        for (int uu = 0; uu < 64; uu++) {
            float4 w4 = *(const float4*)&ws [uu][ty * 4];
            float4 c4 = *(const float4*)&kvs[uu][tx * 4];
            float wr[4] = {w4.x, w4.y, w4.z, w4.w};
            float cr[4] = {c4.x, c4.y, c4.z, c4.w};
#pragma unroll
            for (int i = 0; i < 4; i++)
#pragma unroll
                for (int j = 0; j < 4; j++)
                    acc[i][j] += wr[i] * cr[j];
        }
    }

    float* outp = g_wkv + (size_t)b * NT * NC + h * 64;
#pragma unroll
    for (int i = 0; i < 4; i++) {
        int t = t0 + ty * 4 + i;
        float be = beta[h * NT + t];
        float4 o = {acc[i][0] * be, acc[i][1] * be, acc[i][2] * be, acc[i][3] * be};
        *(float4*)&outp[(size_t)t * NC + tx * 4] = o;
    }
}

// ---------------- rwkv = sigmoid(r) * wkv / sum_k ----------------------------
__global__ void rwkv_elem_kernel() {
    int i = blockIdx.x * 256 + threadIdx.x;
    float r = g_r[i];
    float s = 1.f / (1.f + expf(-r));
    g_rwkv[i] = s * g_wkv[i] / g_sumk[i];
}

// ---------------- host launch -------------------------------------------------
extern "C" void kernel_launch(void* const* d_in, const int* in_sizes, int n_in,
                              void* d_out, int out_size) {
    (void)in_sizes; (void)n_in; (void)out_size;
    const float* x      = (const float*)d_in[0];
    const float* time_w = (const float*)d_in[1];
    const float* alpha  = (const float*)d_in[2];
    const float* beta   = (const float*)d_in[3];
    const float* gamma  = (const float*)d_in[4];
    const float* Wk = (const float*)d_in[5];
    const float* bk = (const float*)d_in[6];
    const float* Wv = (const float*)d_in[7];
    const float* bv = (const float*)d_in[8];
    const float* Wr = (const float*)d_in[9];
    const float* br = (const float*)d_in[10];
    const float* Wo = (const float*)d_in[11];
    const float* bo = (const float*)d_in[12];
    float* out = (float*)d_out;

    float *xs, *kp, *vp, *rp, *rwkv, *WT;
    cudaGetSymbolAddress((void**)&xs,   g_xs);
    cudaGetSymbolAddress((void**)&kp,   g_k);
    cudaGetSymbolAddress((void**)&vp,   g_v);
    cudaGetSymbolAddress((void**)&rp,   g_r);
    cudaGetSymbolAddress((void**)&rwkv, g_rwkv);
    cudaGetSymbolAddress((void**)&WT,   g_WT);
    float* WkT = WT + 0 * NC * NC;
    float* WvT = WT + 1 * NC * NC;
    float* WrT = WT + 2 * NC * NC;
    float* WoT = WT + 3 * NC * NC;

    dim3 tb(32, 8), tg(NC / 32, NC / 32);
    transpose_kernel<<<tg, tb>>>(Wk, WkT);
    transpose_kernel<<<tg, tb>>>(Wv, WvT);
    transpose_kernel<<<tg, tb>>>(Wr, WrT);
    transpose_kernel<<<tg, tb>>>(Wo, WoT);

    build_xs_kernel<<<NM * NC / 256, 256>>>(x);

    dim3 gg(NM / 128, NC / 128);
    gemm_kernel<1><<<gg, 256>>>(xs, WkT, kp, bk, nullptr);
    gemm_kernel<0><<<gg, 256>>>(xs, WvT, vp, bv, nullptr);
    gemm_kernel<0><<<gg, 256>>>(xs, WrT, rp, br, nullptr);

    cumsum_kernel<<<dim3(NC / 256, NB), 256>>>();

    wkv_kernel<<<dim3(NT / 64, NB * NH), 256>>>(time_w, alpha, beta);

    rwkv_elem_kernel<<<NM * NC / 256, 256>>>();

    gemm_kernel<2><<<gg, 256>>>(rwkv, WoT, out, bo, gamma);
}

// round 2
// speedup vs baseline: 1.7319x; 1.7319x over previous
#include <cuda_runtime.h>
#include <cuda_bf16.h>
#include <math.h>
#include <stdint.h>

#define NB 8
#define NT 1024
#define NC 1024
#define NH 16
#define NM (NB*NT)
#define KH 512            // K/2 (bf16 pairs packed along K)

// ---------------- scratch (static device globals, no allocation) -------------
__device__ float    g_k   [NM*NC];
__device__ float    g_v   [NM*NC];
__device__ float    g_r   [NM*NC];
__device__ float    g_sumk[NM*NC];
__device__ float    g_wkv [NM*NC];
__device__ uint32_t g_Ah  [NM*KH];      // packed bf16x2 hi of current A operand
__device__ uint32_t g_Al  [NM*KH];      // packed bf16x2 lo
__device__ uint32_t g_Wh  [4][NC*KH];   // Wk,Wv,Wr,Wo hi splits
__device__ uint32_t g_Wl  [4][NC*KH];

// ---------------- helpers -----------------------------------------------------
__device__ __forceinline__ void split2(float a, float b, uint32_t& hi, uint32_t& lo) {
    float fa = __bfloat162float(__float2bfloat16(a));
    float fb = __bfloat162float(__float2bfloat16(b));
    float la = a - fa, lb = b - fb;
    // pack: low 16 bits = first (even-k) element
    asm("cvt.rn.bf16x2.f32 %0, %1, %2;" : "=r"(hi) : "f"(fb), "f"(fa));
    asm("cvt.rn.bf16x2.f32 %0, %1, %2;" : "=r"(lo) : "f"(lb), "f"(la));
}

__device__ __forceinline__ void mma_bf16(float* c, const uint32_t* a,
                                         uint32_t b0, uint32_t b1) {
    asm volatile(
        "mma.sync.aligned.m16n8k16.row.col.f32.bf16.bf16.f32 "
        "{%0,%1,%2,%3},{%4,%5,%6,%7},{%8,%9},{%0,%1,%2,%3};"
        : "+f"(c[0]), "+f"(c[1]), "+f"(c[2]), "+f"(c[3])
        : "r"(a[0]), "r"(a[1]), "r"(a[2]), "r"(a[3]), "r"(b0), "r"(b1));
}

__device__ __forceinline__ void cpa16(uint32_t d, const void* s) {
    asm volatile("cp.async.cg.shared.global [%0], [%1], 16;" :: "r"(d), "l"(s));
}
#define CP_COMMIT() asm volatile("cp.async.commit_group;")

// ---------------- weight split: W[N,K] fp32 -> packed bf16x2 hi/lo ------------
__global__ void split_w_kernel(const float* __restrict__ W,
                               uint32_t* __restrict__ hi, uint32_t* __restrict__ lo) {
    int i = blockIdx.x * 256 + threadIdx.x;        // over NC*KH
    float2 v = ((const float2*)W)[i];
    split2(v.x, v.y, hi[i], lo[i]);
}

// ---------------- time-shift + split ------------------------------------------
__global__ void build_xs_split_kernel(const float* __restrict__ x) {
    int i = blockIdx.x * 256 + threadIdx.x;        // over NM*KH
    int kk2 = i & (KH - 1);
    int row = i >> 9;                              // b*NT + t
    int t = row & (NT - 1);
    int c = kk2 * 2;
    float a = 0.f, b = 0.f;
    if (c < NC / 2) {
        if (t != 0) {
            float2 v = *(const float2*)(x + (size_t)(row - 1) * NC + c);
            a = v.x; b = v.y;
        }
    } else {
        float2 v = *(const float2*)(x + (size_t)row * NC + c);
        a = v.x; b = v.y;
    }
    split2(a, b, g_Ah[i], g_Al[i]);
}

// ---------------- rwkv = sigmoid(r)*wkv/sumk, then split ----------------------
__global__ void rwkv_split_kernel() {
    int i = blockIdx.x * 256 + threadIdx.x;        // over NM*KH
    int j = i * 2;
    float r0 = g_r[j], r1 = g_r[j + 1];
    float a = (1.f / (1.f + expf(-r0))) * g_wkv[j]     / g_sumk[j];
    float b = (1.f / (1.f + expf(-r1))) * g_wkv[j + 1] / g_sumk[j + 1];
    split2(a, b, g_Ah[i], g_Al[i]);
}

// ---------------- bf16x3 tensor-core GEMM  C[M,N] = A[M,K] * W[N,K]^T + bias --
// EPI: 0 plain, 1 exp(clip(.,-60,30)), 2 *gamma[t]
#define SSTG 1536   // u32 per stage per array: 128 rows * 12 (8 data + 4 pad)

template<int EPI>
__global__ void __launch_bounds__(256) gemm_bf16x3(
    const uint32_t* __restrict__ Ah, const uint32_t* __restrict__ Al,
    const uint32_t* __restrict__ Bh, const uint32_t* __restrict__ Bl,
    float* __restrict__ C, const float* __restrict__ bias,
    const float* __restrict__ gamma)
{
    extern __shared__ uint32_t sm[];
    uint32_t* SAh = sm;                // [2][SSTG]
    uint32_t* SAl = sm + 2 * SSTG;
    uint32_t* SBh = sm + 4 * SSTG;
    uint32_t* SBl = sm + 6 * SSTG;

    int tid = threadIdx.x;
    int m0 = blockIdx.x * 128, n0 = blockIdx.y * 128;

    // ---- async-copy mapping: thread -> (row, 4-u32 group) ----
    int lrow = tid >> 1;
    int lg = (tid & 1) * 4;
    const uint32_t* pAh = Ah + (size_t)(m0 + lrow) * KH + lg;
    const uint32_t* pAl = Al + (size_t)(m0 + lrow) * KH + lg;
    const uint32_t* pBh = Bh + (size_t)(n0 + lrow) * KH + lg;
    const uint32_t* pBl = Bl + (size_t)(n0 + lrow) * KH + lg;
    uint32_t sbase = (uint32_t)__cvta_generic_to_shared(sm) + (lrow * 12 + lg) * 4;

    int lane = tid & 31, warp = tid >> 5;
    int wm = (warp >> 1) * 32, wn = (warp & 1) * 64;
    int r = lane >> 2, cc = lane & 3;

    float acc[2][8][4];
#pragma unroll
    for (int a = 0; a < 2; a++)
#pragma unroll
        for (int b = 0; b < 8; b++)
#pragma unroll
            for (int q = 0; q < 4; q++) acc[a][b][q] = 0.f;

    // prologue: stage 0
    {
        uint32_t d = sbase;
        cpa16(d,                pAh);
        cpa16(d + 2 * SSTG * 4, pAl);
        cpa16(d + 4 * SSTG * 4, pBh);
        cpa16(d + 6 * SSTG * 4, pBl);
        CP_COMMIT();
    }

    for (int kt = 0; kt < 64; kt++) {
        if (kt) __syncthreads();                      // buffer (kt+1)&1 free
        if (kt + 1 < 64) {
            uint32_t d = sbase + ((kt + 1) & 1) * SSTG * 4;
            int o = (kt + 1) * 8;
            cpa16(d,                pAh + o);
            cpa16(d + 2 * SSTG * 4, pAl + o);
            cpa16(d + 4 * SSTG * 4, pBh + o);
            cpa16(d + 6 * SSTG * 4, pBl + o);
            CP_COMMIT();
            asm volatile("cp.async.wait_group 1;");
        } else {
            asm volatile("cp.async.wait_group 0;");
        }
        __syncthreads();

        int st = (kt & 1) * SSTG;
        uint32_t ah[2][4], al[2][4];
#pragma unroll
        for (int mi = 0; mi < 2; mi++) {
            int rb  = st + (wm + mi * 16 + r) * 12;
            int rb8 = rb + 8 * 12;
            ah[mi][0] = SAh[rb + cc];     ah[mi][1] = SAh[rb8 + cc];
            ah[mi][2] = SAh[rb + cc + 4]; ah[mi][3] = SAh[rb8 + cc + 4];
            al[mi][0] = SAl[rb + cc];     al[mi][1] = SAl[rb8 + cc];
            al[mi][2] = SAl[rb + cc + 4]; al[mi][3] = SAl[rb8 + cc + 4];
        }
#pragma unroll
        for (int nj = 0; nj < 8; nj++) {
            int nb = st + (wn + nj * 8 + r) * 12;
            uint32_t bh0 = SBh[nb + cc], bh1 = SBh[nb + cc + 4];
            uint32_t bl0 = SBl[nb + cc], bl1 = SBl[nb + cc + 4];
#pragma unroll
            for (int mi = 0; mi < 2; mi++) {
                mma_bf16(acc[mi][nj], ah[mi], bh0, bh1);
                mma_bf16(acc[mi][nj], al[mi], bh0, bh1);
                mma_bf16(acc[mi][nj], ah[mi], bl0, bl1);
            }
        }
    }

    // ---- epilogue ----
#pragma unroll
    for (int mi = 0; mi < 2; mi++) {
        int mlo = m0 + wm + mi * 16 + r;
        int mhi = mlo + 8;
        float glo = 1.f, ghi = 1.f;
        if (EPI == 2) { glo = gamma[mlo & (NT - 1)]; ghi = gamma[mhi & (NT - 1)]; }
#pragma unroll
        for (int nj = 0; nj < 8; nj++) {
            int col = n0 + wn + nj * 8 + cc * 2;
            float b0 = bias[col], b1 = bias[col + 1];
            float v0 = acc[mi][nj][0] + b0, v1 = acc[mi][nj][1] + b1;
            float v2 = acc[mi][nj][2] + b0, v3 = acc[mi][nj][3] + b1;
            if (EPI == 1) {
                v0 = expf(fminf(fmaxf(v0, -60.f), 30.f));
                v1 = expf(fminf(fmaxf(v1, -60.f), 30.f));
                v2 = expf(fminf(fmaxf(v2, -60.f), 30.f));
                v3 = expf(fminf(fmaxf(v3, -60.f), 30.f));
            }
            if (EPI == 2) { v0 *= glo; v1 *= glo; v2 *= ghi; v3 *= ghi; }
            float2 o01 = {v0, v1}, o23 = {v2, v3};
            *(float2*)&C[(size_t)mlo * NC + col] = o01;
            *(float2*)&C[(size_t)mhi * NC + col] = o23;
        }
    }
}

// ---------------- cumsum over t (per (b,channel)) ----------------------------
__global__ void cumsum_kernel() {
    int c = blockIdx.x * 256 + threadIdx.x;
    int b = blockIdx.y;
    const float* src = g_k    + (size_t)b * NT * NC + c;
    float*       dst = g_sumk + (size_t)b * NT * NC + c;
    float s = 0.f;
    for (int t0 = 0; t0 < NT; t0 += 16) {
        float buf[16];
#pragma unroll
        for (int j = 0; j < 16; j++) buf[j] = src[(size_t)(t0 + j) * NC];
#pragma unroll
        for (int j = 0; j < 16; j++) { s += buf[j]; dst[(size_t)(t0 + j) * NC] = s; }
    }
}

// ---------------- wkv: causal per-head decay matmul --------------------------
__global__ void __launch_bounds__(256) wkv_kernel(
    const float* __restrict__ time_w, const float* __restrict__ alpha,
    const float* __restrict__ beta)
{
    __shared__ float tw[NT];
    __shared__ float ws [64][68];
    __shared__ float kvs[64][68];

    int tt = blockIdx.x;
    int b = blockIdx.y >> 4, h = blockIdx.y & 15;
    int tid = threadIdx.x;

    for (int i = tid; i < NT; i += 256) tw[i] = time_w[h * NT + i];

    int t0 = tt * 64;
    int ty = tid >> 4, tx = tid & 15;
    float acc[4][4];
#pragma unroll
    for (int i = 0; i < 4; i++)
#pragma unroll
        for (int j = 0; j < 4; j++) acc[i][j] = 0.f;

    const float* kbase = g_k + (size_t)b * NT * NC + h * 64;
    const float* vbase = g_v + (size_t)b * NT * NC + h * 64;

    for (int ut = 0; ut <= tt; ut++) {
        int u0 = ut * 64;
        __syncthreads();
#pragma unroll 4
        for (int rr = 0; rr < 16; rr++) {
            int i = tid + rr * 256;
            int uu = i >> 6, ccx = i & 63;
            int u = u0 + uu;
            kvs[uu][ccx] = kbase[(size_t)u * NC + ccx] * vbase[(size_t)u * NC + ccx]
                         * alpha[h * NT + u];
            int t = t0 + ccx;
            float wv = 0.f;
            if (u <= t) wv = tw[1023 - t + u];
            ws[uu][ccx] = wv;
        }
        __syncthreads();
#pragma unroll
        for (int uu = 0; uu < 64; uu++) {
            float4 w4 = *(const float4*)&ws [uu][ty * 4];
            float4 c4 = *(const float4*)&kvs[uu][tx * 4];
            float wr[4] = {w4.x, w4.y, w4.z, w4.w};
            float cr[4] = {c4.x, c4.y, c4.z, c4.w};
#pragma unroll
            for (int i = 0; i < 4; i++)
#pragma unroll
                for (int j = 0; j < 4; j++)
                    acc[i][j] += wr[i] * cr[j];
        }
    }

    float* outp = g_wkv + (size_t)b * NT * NC + h * 64;
#pragma unroll
    for (int i = 0; i < 4; i++) {
        int t = t0 + ty * 4 + i;
        float be = beta[h * NT + t];
        float4 o = {acc[i][0] * be, acc[i][1] * be, acc[i][2] * be, acc[i][3] * be};
        *(float4*)&outp[(size_t)t * NC + tx * 4] = o;
    }
}

// ---------------- host launch -------------------------------------------------
extern "C" void kernel_launch(void* const* d_in, const int* in_sizes, int n_in,
                              void* d_out, int out_size) {
    (void)in_sizes; (void)n_in; (void)out_size;
    const float* x      = (const float*)d_in[0];
    const float* time_w = (const float*)d_in[1];
    const float* alpha  = (const float*)d_in[2];
    const float* beta   = (const float*)d_in[3];
    const float* gamma  = (const float*)d_in[4];
    const float* Wk = (const float*)d_in[5];
    const float* bk = (const float*)d_in[6];
    const float* Wv = (const float*)d_in[7];
    const float* bv = (const float*)d_in[8];
    const float* Wr = (const float*)d_in[9];
    const float* br = (const float*)d_in[10];
    const float* Wo = (const float*)d_in[11];
    const float* bo = (const float*)d_in[12];
    float* out = (float*)d_out;

    float *kp, *vp, *rp;
    uint32_t *Ah, *Al, *Wh, *Wl;
    cudaGetSymbolAddress((void**)&kp, g_k);
    cudaGetSymbolAddress((void**)&vp, g_v);
    cudaGetSymbolAddress((void**)&rp, g_r);
    cudaGetSymbolAddress((void**)&Ah, g_Ah);
    cudaGetSymbolAddress((void**)&Al, g_Al);
    cudaGetSymbolAddress((void**)&Wh, g_Wh);
    cudaGetSymbolAddress((void**)&Wl, g_Wl);

    const float* Ws[4] = {Wk, Wv, Wr, Wo};
    for (int i = 0; i < 4; i++)
        split_w_kernel<<<NC * KH / 256, 256>>>(Ws[i], Wh + i * NC * KH, Wl + i * NC * KH);

    build_xs_split_kernel<<<NM * KH / 256, 256>>>(x);

    dim3 gg(NM / 128, NC / 128);
    size_t smem = 8 * SSTG * 4;
    gemm_bf16x3<1><<<gg, 256, smem>>>(Ah, Al, Wh + 0 * NC * KH, Wl + 0 * NC * KH, kp, bk, nullptr);
    gemm_bf16x3<0><<<gg, 256, smem>>>(Ah, Al, Wh + 1 * NC * KH, Wl + 1 * NC * KH, vp, bv, nullptr);
    gemm_bf16x3<0><<<gg, 256, smem>>>(Ah, Al, Wh + 2 * NC * KH, Wl + 2 * NC * KH, rp, br, nullptr);

    cumsum_kernel<<<dim3(NC / 256, NB), 256>>>();

    wkv_kernel<<<dim3(NT / 64, NB * NH), 256>>>(time_w, alpha, beta);

    rwkv_split_kernel<<<NM * KH / 256, 256>>>();

    gemm_bf16x3<2><<<gg, 256, smem>>>(Ah, Al, Wh + 3 * NC * KH, Wl + 3 * NC * KH, out, bo, gamma);
}

// round 3
// speedup vs baseline: 1.9557x; 1.1292x over previous
#include <cuda_runtime.h>
#include <cuda_bf16.h>
#include <math.h>
#include <stdint.h>

#define NB 8
#define NT 1024
#define NC 1024
#define NH 16
#define NM (NB*NT)
#define KH 512            // K/2 (bf16 pairs packed along K)

// ---------------- scratch (static device globals, no allocation) -------------
__device__ float    g_k   [NM*NC];
__device__ float    g_v   [NM*NC];
__device__ float    g_r   [NM*NC];
__device__ float    g_sumk[NM*NC];
__device__ float    g_wkv [NM*NC];
__device__ uint32_t g_Ah  [NM*KH];        // packed bf16x2 hi of current A operand
__device__ uint32_t g_Al  [NM*KH];        // packed bf16x2 lo
__device__ uint32_t g_Wh  [4][NC*KH];     // Wk,Wv,Wr,Wo hi splits
__device__ uint32_t g_Wl  [4][NC*KH];
__device__ uint32_t g_WWh [NH*NT*KH];     // decay matrix W[h][t][u] hi (packed u-pairs)
__device__ uint32_t g_WWl [NH*NT*KH];     // decay matrix lo
__device__ uint32_t g_kvTh[NB*NH*64*KH];  // kv^T [bh][c][u-pairs] hi
__device__ uint32_t g_kvTl[NB*NH*64*KH];  // kv^T lo

// ---------------- helpers -----------------------------------------------------
__device__ __forceinline__ void split2(float a, float b, uint32_t& hi, uint32_t& lo) {
    float fa = __bfloat162float(__float2bfloat16(a));
    float fb = __bfloat162float(__float2bfloat16(b));
    float la = a - fa, lb = b - fb;
    asm("cvt.rn.bf16x2.f32 %0, %1, %2;" : "=r"(hi) : "f"(fb), "f"(fa));
    asm("cvt.rn.bf16x2.f32 %0, %1, %2;" : "=r"(lo) : "f"(lb), "f"(la));
}

__device__ __forceinline__ void mma_bf16(float* c, const uint32_t* a,
                                         uint32_t b0, uint32_t b1) {
    asm volatile(
        "mma.sync.aligned.m16n8k16.row.col.f32.bf16.bf16.f32 "
        "{%0,%1,%2,%3},{%4,%5,%6,%7},{%8,%9},{%0,%1,%2,%3};"
        : "+f"(c[0]), "+f"(c[1]), "+f"(c[2]), "+f"(c[3])
        : "r"(a[0]), "r"(a[1]), "r"(a[2]), "r"(a[3]), "r"(b0), "r"(b1));
}

__device__ __forceinline__ void cpa16(uint32_t d, const void* s) {
    asm volatile("cp.async.cg.shared.global [%0], [%1], 16;" :: "r"(d), "l"(s));
}
#define CP_COMMIT() asm volatile("cp.async.commit_group;")

// ---------------- weight split: W[N,K] fp32 -> packed bf16x2 hi/lo ------------
__global__ void split_w_kernel(const float* __restrict__ W,
                               uint32_t* __restrict__ hi, uint32_t* __restrict__ lo) {
    int i = blockIdx.x * 256 + threadIdx.x;
    float2 v = ((const float2*)W)[i];
    split2(v.x, v.y, hi[i], lo[i]);
}

// ---------------- decay matrix precompute: W[h,t,u]=tw[h,1023-t+u]*alpha[h,u] --
__global__ void build_W_kernel(const float* __restrict__ tw,
                               const float* __restrict__ alpha) {
    int i = blockIdx.x * 256 + threadIdx.x;       // over NH*NT*KH
    int u = (i & (KH - 1)) * 2;
    int t = (i >> 9) & (NT - 1);
    int h = i >> 19;
    float w0 = 0.f, w1 = 0.f;
    if (u <= t)     w0 = tw[h * NT + 1023 - t + u]     * alpha[h * NT + u];
    if (u + 1 <= t) w1 = tw[h * NT + 1023 - t + u + 1] * alpha[h * NT + u + 1];
    split2(w0, w1, g_WWh[i], g_WWl[i]);
}

// ---------------- time-shift + split ------------------------------------------
__global__ void build_xs_split_kernel(const float* __restrict__ x) {
    int i = blockIdx.x * 256 + threadIdx.x;       // over NM*KH
    int kk2 = i & (KH - 1);
    int row = i >> 9;
    int t = row & (NT - 1);
    int c = kk2 * 2;
    float a = 0.f, b = 0.f;
    if (c < NC / 2) {
        if (t != 0) {
            float2 v = *(const float2*)(x + (size_t)(row - 1) * NC + c);
            a = v.x; b = v.y;
        }
    } else {
        float2 v = *(const float2*)(x + (size_t)row * NC + c);
        a = v.x; b = v.y;
    }
    split2(a, b, g_Ah[i], g_Al[i]);
}

// ---------------- rwkv = sigmoid(r)*wkv/sumk, then split ----------------------
__global__ void rwkv_split_kernel() {
    int i = blockIdx.x * 256 + threadIdx.x;
    int j = i * 2;
    float r0 = g_r[j], r1 = g_r[j + 1];
    float a = (1.f / (1.f + expf(-r0))) * g_wkv[j]     / g_sumk[j];
    float b = (1.f / (1.f + expf(-r1))) * g_wkv[j + 1] / g_sumk[j + 1];
    split2(a, b, g_Ah[i], g_Al[i]);
}

// ---------------- kv^T split: kv[b,u,h,c] -> kvT[bh][c][u] bf16 hi/lo ---------
__global__ void kvt_split_kernel() {
    __shared__ float skv[64][65];
    int ut = blockIdx.x;                  // u tile (0..15)
    int bh = blockIdx.y;
    int b = bh >> 4, h = bh & 15;
    int tid = threadIdx.x;
    int u0 = ut * 64;
    const float* kb = g_k + ((size_t)(b * NT + u0)) * NC + h * 64;
    const float* vb = g_v + ((size_t)(b * NT + u0)) * NC + h * 64;
#pragma unroll
    for (int rr = 0; rr < 16; rr++) {
        int i = tid + rr * 256;
        int uu = i >> 6, c = i & 63;
        skv[uu][c] = kb[(size_t)uu * NC + c] * vb[(size_t)uu * NC + c];
    }
    __syncthreads();
    uint32_t* oh = g_kvTh + (size_t)bh * 64 * KH + ut * 32;
    uint32_t* ol = g_kvTl + (size_t)bh * 64 * KH + ut * 32;
#pragma unroll
    for (int rr = 0; rr < 8; rr++) {
        int j = tid + rr * 256;
        int c = j >> 5, g = j & 31;
        uint32_t hi, lo;
        split2(skv[g * 2][c], skv[g * 2 + 1][c], hi, lo);
        oh[(size_t)c * KH + g] = hi;
        ol[(size_t)c * KH + g] = lo;
    }
}

// ---------------- wkv via tensor cores (bf16x3, causal) ------------------------
#define WR 20                 // row stride in u32 (16 data + 4 pad)
#define WST (64*WR)           // u32 per array per stage

__global__ void __launch_bounds__(256) wkv_mma_kernel(const float* __restrict__ beta) {
    __shared__ uint32_t smw[2 * 4 * WST];     // 2 stages x (Wh,Wl,Kh,Kl) = 40KB
    int tt = blockIdx.x, bh = blockIdx.y;
    int b = bh >> 4, h = bh & 15;
    int t0 = tt * 64;
    int tid = threadIdx.x;
    int lrow = tid >> 2, lq = (tid & 3) * 4;

    const uint32_t* pWh = g_WWh + ((size_t)h * NT + t0 + lrow) * KH + lq;
    const uint32_t* pWl = g_WWl + ((size_t)h * NT + t0 + lrow) * KH + lq;
    const uint32_t* pKh = g_kvTh + ((size_t)bh * 64 + lrow) * KH + lq;
    const uint32_t* pKl = g_kvTl + ((size_t)bh * 64 + lrow) * KH + lq;
    uint32_t sb = (uint32_t)__cvta_generic_to_shared(smw) + (lrow * WR + lq) * 4;

    int lane = tid & 31, warp = tid >> 5;
    int wm = (warp >> 1) * 16, wn = (warp & 1) * 32;
    int r = lane >> 2, cc = lane & 3;

    float acc[4][4];
#pragma unroll
    for (int i = 0; i < 4; i++)
#pragma unroll
        for (int j = 0; j < 4; j++) acc[i][j] = 0.f;

    int nut = 2 * (tt + 1);     // 32-u tiles (causal)

    // prologue
    cpa16(sb,               pWh);
    cpa16(sb + WST * 4,     pWl);
    cpa16(sb + 2 * WST * 4, pKh);
    cpa16(sb + 3 * WST * 4, pKl);
    CP_COMMIT();

    for (int ut = 0; ut < nut; ut++) {
        if (ut) __syncthreads();
        if (ut + 1 < nut) {
            uint32_t d = sb + ((ut + 1) & 1) * 4 * WST * 4;
            int o = (ut + 1) * 16;
            cpa16(d,               pWh + o);
            cpa16(d + WST * 4,     pWl + o);
            cpa16(d + 2 * WST * 4, pKh + o);
            cpa16(d + 3 * WST * 4, pKl + o);
            CP_COMMIT();
            asm volatile("cp.async.wait_group 1;");
        } else {
            asm volatile("cp.async.wait_group 0;");
        }
        __syncthreads();

        const uint32_t* S   = smw + (ut & 1) * 4 * WST;
        const uint32_t* SWh = S;
        const uint32_t* SWl = S + WST;
        const uint32_t* SKh = S + 2 * WST;
        const uint32_t* SKl = S + 3 * WST;
#pragma unroll
        for (int ks = 0; ks < 2; ks++) {
            int rb = (wm + r) * WR + ks * 8;
            uint32_t ah[4], al[4];
            ah[0] = SWh[rb + cc];          ah[1] = SWh[rb + 8 * WR + cc];
            ah[2] = SWh[rb + cc + 4];      ah[3] = SWh[rb + 8 * WR + cc + 4];
            al[0] = SWl[rb + cc];          al[1] = SWl[rb + 8 * WR + cc];
            al[2] = SWl[rb + cc + 4];      al[3] = SWl[rb + 8 * WR + cc + 4];
#pragma unroll
            for (int nj = 0; nj < 4; nj++) {
                int nb = (wn + nj * 8 + r) * WR + ks * 8;
                uint32_t bh0 = SKh[nb + cc], bh1 = SKh[nb + cc + 4];
                uint32_t bl0 = SKl[nb + cc], bl1 = SKl[nb + cc + 4];
                mma_bf16(acc[nj], ah, bh0, bh1);
                mma_bf16(acc[nj], al, bh0, bh1);
                mma_bf16(acc[nj], ah, bl0, bl1);
            }
        }
    }

    // epilogue: multiply beta[t], write to g_wkv
    int tlo = t0 + wm + r, thi = tlo + 8;
    float be_lo = beta[h * NT + tlo], be_hi = beta[h * NT + thi];
    float* orow_lo = g_wkv + ((size_t)(b * NT + tlo)) * NC + h * 64;
    float* orow_hi = g_wkv + ((size_t)(b * NT + thi)) * NC + h * 64;
#pragma unroll
    for (int nj = 0; nj < 4; nj++) {
        int col = wn + nj * 8 + cc * 2;
        float2 o1 = {acc[nj][0] * be_lo, acc[nj][1] * be_lo};
        float2 o2 = {acc[nj][2] * be_hi, acc[nj][3] * be_hi};
        *(float2*)&orow_lo[col] = o1;
        *(float2*)&orow_hi[col] = o2;
    }
}

// ---------------- bf16x3 tensor-core GEMM  C[M,N] = A[M,K] * W[N,K]^T + bias --
// EPI: 0 plain, 1 exp(clip(.,-60,30)), 2 *gamma[t]
#define SSTG 1536   // u32 per stage per array: 128 rows * 12 (8 data + 4 pad)

template<int EPI>
__global__ void __launch_bounds__(256) gemm_bf16x3(
    const uint32_t* __restrict__ Ah, const uint32_t* __restrict__ Al,
    const uint32_t* __restrict__ Bh, const uint32_t* __restrict__ Bl,
    float* __restrict__ C, const float* __restrict__ bias,
    const float* __restrict__ gamma)
{
    extern __shared__ uint32_t sm[];
    uint32_t* SAh = sm;
    uint32_t* SAl = sm + 2 * SSTG;
    uint32_t* SBh = sm + 4 * SSTG;
    uint32_t* SBl = sm + 6 * SSTG;

    int tid = threadIdx.x;
    int m0 = blockIdx.x * 128, n0 = blockIdx.y * 128;

    int lrow = tid >> 1;
    int lg = (tid & 1) * 4;
    const uint32_t* pAh = Ah + (size_t)(m0 + lrow) * KH + lg;
    const uint32_t* pAl = Al + (size_t)(m0 + lrow) * KH + lg;
    const uint32_t* pBh = Bh + (size_t)(n0 + lrow) * KH + lg;
    const uint32_t* pBl = Bl + (size_t)(n0 + lrow) * KH + lg;
    uint32_t sbase = (uint32_t)__cvta_generic_to_shared(sm) + (lrow * 12 + lg) * 4;

    int lane = tid & 31, warp = tid >> 5;
    int wm = (warp >> 1) * 32, wn = (warp & 1) * 64;
    int r = lane >> 2, cc = lane & 3;

    float acc[2][8][4];
#pragma unroll
    for (int a = 0; a < 2; a++)
#pragma unroll
        for (int b = 0; b < 8; b++)
#pragma unroll
            for (int q = 0; q < 4; q++) acc[a][b][q] = 0.f;

    {
        uint32_t d = sbase;
        cpa16(d,                pAh);
        cpa16(d + 2 * SSTG * 4, pAl);
        cpa16(d + 4 * SSTG * 4, pBh);
        cpa16(d + 6 * SSTG * 4, pBl);
        CP_COMMIT();
    }

    for (int kt = 0; kt < 64; kt++) {
        if (kt) __syncthreads();
        if (kt + 1 < 64) {
            uint32_t d = sbase + ((kt + 1) & 1) * SSTG * 4;
            int o = (kt + 1) * 8;
            cpa16(d,                pAh + o);
            cpa16(d + 2 * SSTG * 4, pAl + o);
            cpa16(d + 4 * SSTG * 4, pBh + o);
            cpa16(d + 6 * SSTG * 4, pBl + o);
            CP_COMMIT();
            asm volatile("cp.async.wait_group 1;");
        } else {
            asm volatile("cp.async.wait_group 0;");
        }
        __syncthreads();

        int st = (kt & 1) * SSTG;
        uint32_t ah[2][4], al[2][4];
#pragma unroll
        for (int mi = 0; mi < 2; mi++) {
            int rb  = st + (wm + mi * 16 + r) * 12;
            int rb8 = rb + 8 * 12;
            ah[mi][0] = SAh[rb + cc];     ah[mi][1] = SAh[rb8 + cc];
            ah[mi][2] = SAh[rb + cc + 4]; ah[mi][3] = SAh[rb8 + cc + 4];
            al[mi][0] = SAl[rb + cc];     al[mi][1] = SAl[rb8 + cc];
            al[mi][2] = SAl[rb + cc + 4]; al[mi][3] = SAl[rb8 + cc + 4];
        }
#pragma unroll
        for (int nj = 0; nj < 8; nj++) {
            int nb = st + (wn + nj * 8 + r) * 12;
            uint32_t bh0 = SBh[nb + cc], bh1 = SBh[nb + cc + 4];
            uint32_t bl0 = SBl[nb + cc], bl1 = SBl[nb + cc + 4];
#pragma unroll
            for (int mi = 0; mi < 2; mi++) {
                mma_bf16(acc[mi][nj], ah[mi], bh0, bh1);
                mma_bf16(acc[mi][nj], al[mi], bh0, bh1);
                mma_bf16(acc[mi][nj], ah[mi], bl0, bl1);
            }
        }
    }

#pragma unroll
    for (int mi = 0; mi < 2; mi++) {
        int mlo = m0 + wm + mi * 16 + r;
        int mhi = mlo + 8;
        float glo = 1.f, ghi = 1.f;
        if (EPI == 2) { glo = gamma[mlo & (NT - 1)]; ghi = gamma[mhi & (NT - 1)]; }
#pragma unroll
        for (int nj = 0; nj < 8; nj++) {
            int col = n0 + wn + nj * 8 + cc * 2;
            float b0 = bias[col], b1 = bias[col + 1];
            float v0 = acc[mi][nj][0] + b0, v1 = acc[mi][nj][1] + b1;
            float v2 = acc[mi][nj][2] + b0, v3 = acc[mi][nj][3] + b1;
            if (EPI == 1) {
                v0 = expf(fminf(fmaxf(v0, -60.f), 30.f));
                v1 = expf(fminf(fmaxf(v1, -60.f), 30.f));
                v2 = expf(fminf(fmaxf(v2, -60.f), 30.f));
                v3 = expf(fminf(fmaxf(v3, -60.f), 30.f));
            }
            if (EPI == 2) { v0 *= glo; v1 *= glo; v2 *= ghi; v3 *= ghi; }
            float2 o01 = {v0, v1}, o23 = {v2, v3};
            *(float2*)&C[(size_t)mlo * NC + col] = o01;
            *(float2*)&C[(size_t)mhi * NC + col] = o23;
        }
    }
}

// ---------------- cumsum over t (per (b,channel)) ----------------------------
__global__ void cumsum_kernel() {
    int c = blockIdx.x * 256 + threadIdx.x;
    int b = blockIdx.y;
    const float* src = g_k    + (size_t)b * NT * NC + c;
    float*       dst = g_sumk + (size_t)b * NT * NC + c;
    float s = 0.f;
    for (int t0 = 0; t0 < NT; t0 += 16) {
        float buf[16];
#pragma unroll
        for (int j = 0; j < 16; j++) buf[j] = src[(size_t)(t0 + j) * NC];
#pragma unroll
        for (int j = 0; j < 16; j++) { s += buf[j]; dst[(size_t)(t0 + j) * NC] = s; }
    }
}

// ---------------- host launch -------------------------------------------------
extern "C" void kernel_launch(void* const* d_in, const int* in_sizes, int n_in,
                              void* d_out, int out_size) {
    (void)in_sizes; (void)n_in; (void)out_size;
    const float* x      = (const float*)d_in[0];
    const float* time_w = (const float*)d_in[1];
    const float* alpha  = (const float*)d_in[2];
    const float* beta   = (const float*)d_in[3];
    const float* gamma  = (const float*)d_in[4];
    const float* Wk = (const float*)d_in[5];
    const float* bk = (const float*)d_in[6];
    const float* Wv = (const float*)d_in[7];
    const float* bv = (const float*)d_in[8];
    const float* Wr = (const float*)d_in[9];
    const float* br = (const float*)d_in[10];
    const float* Wo = (const float*)d_in[11];
    const float* bo = (const float*)d_in[12];
    float* out = (float*)d_out;

    float *kp, *vp, *rp;
    uint32_t *Ah, *Al, *Wh, *Wl;
    cudaGetSymbolAddress((void**)&kp, g_k);
    cudaGetSymbolAddress((void**)&vp, g_v);
    cudaGetSymbolAddress((void**)&rp, g_r);
    cudaGetSymbolAddress((void**)&Ah, g_Ah);
    cudaGetSymbolAddress((void**)&Al, g_Al);
    cudaGetSymbolAddress((void**)&Wh, g_Wh);
    cudaGetSymbolAddress((void**)&Wl, g_Wl);

    const float* Ws[4] = {Wk, Wv, Wr, Wo};
    for (int i = 0; i < 4; i++)
        split_w_kernel<<<NC * KH / 256, 256>>>(Ws[i], Wh + i * NC * KH, Wl + i * NC * KH);

    build_W_kernel<<<NH * NT * KH / 256, 256>>>(time_w, alpha);

    build_xs_split_kernel<<<NM * KH / 256, 256>>>(x);

    dim3 gg(NM / 128, NC / 128);
    size_t smem = 8 * SSTG * 4;
    gemm_bf16x3<1><<<gg, 256, smem>>>(Ah, Al, Wh + 0 * NC * KH, Wl + 0 * NC * KH, kp, bk, nullptr);
    gemm_bf16x3<0><<<gg, 256, smem>>>(Ah, Al, Wh + 1 * NC * KH, Wl + 1 * NC * KH, vp, bv, nullptr);
    gemm_bf16x3<0><<<gg, 256, smem>>>(Ah, Al, Wh + 2 * NC * KH, Wl + 2 * NC * KH, rp, br, nullptr);

    cumsum_kernel<<<dim3(NC / 256, NB), 256>>>();

    kvt_split_kernel<<<dim3(NT / 64, NB * NH), 256>>>();

    wkv_mma_kernel<<<dim3(NT / 64, NB * NH), 256>>>(beta);

    rwkv_split_kernel<<<NM * KH / 256, 256>>>();

    gemm_bf16x3<2><<<gg, 256, smem>>>(Ah, Al, Wh + 3 * NC * KH, Wl + 3 * NC * KH, out, bo, gamma);
}

// round 4
// speedup vs baseline: 2.2415x; 1.1462x over previous
#include <cuda_runtime.h>
#include <cuda_bf16.h>
#include <math.h>
#include <stdint.h>

#define NB 8
#define NT 1024
#define NC 1024
#define NH 16
#define NM (NB*NT)
#define KH 512            // K/2 (bf16 pairs packed along K)
#define NSEG 8
#define TSEG (NT/NSEG)

// ---------------- scratch (static device globals, no allocation) -------------
__device__ float    g_kvr [3*NM*NC];      // k, v, r
__device__ float    g_sumk[NM*NC];        // per-segment local cumsum
__device__ float    g_segtot[NB*NSEG*NC];
__device__ float    g_segoff[NB*NSEG*NC];
__device__ float    g_wkv [NM*NC];
__device__ uint32_t g_Ah  [NM*KH];        // packed bf16x2 hi of current A operand
__device__ uint32_t g_Al  [NM*KH];        // packed bf16x2 lo
__device__ uint32_t g_Wh  [4*NC*KH];      // Wk,Wv,Wr,Wo hi splits (contiguous)
__device__ uint32_t g_Wl  [4*NC*KH];
__device__ uint32_t g_WWh [NH*NT*KH];     // decay matrix W[h][t][u] hi
__device__ uint32_t g_WWl [NH*NT*KH];
__device__ uint32_t g_kvTh[NB*NH*64*KH];  // kv^T [bh][c][u-pairs] hi
__device__ uint32_t g_kvTl[NB*NH*64*KH];

// ---------------- helpers -----------------------------------------------------
__device__ __forceinline__ void split2(float a, float b, uint32_t& hi, uint32_t& lo) {
    float fa = __bfloat162float(__float2bfloat16(a));
    float fb = __bfloat162float(__float2bfloat16(b));
    float la = a - fa, lb = b - fb;
    asm("cvt.rn.bf16x2.f32 %0, %1, %2;" : "=r"(hi) : "f"(fb), "f"(fa));
    asm("cvt.rn.bf16x2.f32 %0, %1, %2;" : "=r"(lo) : "f"(lb), "f"(la));
}

__device__ __forceinline__ void mma_bf16(float* c, const uint32_t* a,
                                         uint32_t b0, uint32_t b1) {
    asm volatile(
        "mma.sync.aligned.m16n8k16.row.col.f32.bf16.bf16.f32 "
        "{%0,%1,%2,%3},{%4,%5,%6,%7},{%8,%9},{%0,%1,%2,%3};"
        : "+f"(c[0]), "+f"(c[1]), "+f"(c[2]), "+f"(c[3])
        : "r"(a[0]), "r"(a[1]), "r"(a[2]), "r"(a[3]), "r"(b0), "r"(b1));
}

__device__ __forceinline__ void cpa16(uint32_t d, const void* s) {
    asm volatile("cp.async.cg.shared.global [%0], [%1], 16;" :: "r"(d), "l"(s));
}
#define CP_COMMIT() asm volatile("cp.async.commit_group;")

// ---------------- weight split: all 4 weights in one launch -------------------
__global__ void split_w_all_kernel(const float* __restrict__ W0,
                                   const float* __restrict__ W1,
                                   const float* __restrict__ W2,
                                   const float* __restrict__ W3) {
    int i = blockIdx.x * 256 + threadIdx.x;       // over 4*NC*KH
    int w = i >> 19;                              // NC*KH = 512K
    int j = i & (NC * KH - 1);
    const float* W = (w == 0) ? W0 : (w == 1) ? W1 : (w == 2) ? W2 : W3;
    float2 v = ((const float2*)W)[j];
    split2(v.x, v.y, g_Wh[i], g_Wl[i]);
}

// ---------------- decay matrix precompute --------------------------------------
__global__ void build_W_kernel(const float* __restrict__ tw,
                               const float* __restrict__ alpha) {
    int i = blockIdx.x * 256 + threadIdx.x;       // over NH*NT*KH
    int u = (i & (KH - 1)) * 2;
    int t = (i >> 9) & (NT - 1);
    int h = i >> 19;
    float w0 = 0.f, w1 = 0.f;
    if (u <= t)     w0 = tw[h * NT + 1023 - t + u]     * alpha[h * NT + u];
    if (u + 1 <= t) w1 = tw[h * NT + 1023 - t + u + 1] * alpha[h * NT + u + 1];
    split2(w0, w1, g_WWh[i], g_WWl[i]);
}

// ---------------- time-shift + split ------------------------------------------
__global__ void build_xs_split_kernel(const float* __restrict__ x) {
    int i = blockIdx.x * 256 + threadIdx.x;       // over NM*KH
    int kk2 = i & (KH - 1);
    int row = i >> 9;
    int t = row & (NT - 1);
    int c = kk2 * 2;
    float a = 0.f, b = 0.f;
    if (c < NC / 2) {
        if (t != 0) {
            float2 v = *(const float2*)(x + (size_t)(row - 1) * NC + c);
            a = v.x; b = v.y;
        }
    } else {
        float2 v = *(const float2*)(x + (size_t)row * NC + c);
        a = v.x; b = v.y;
    }
    split2(a, b, g_Ah[i], g_Al[i]);
}

// ---------------- cumsum phase A: per-segment local scans ---------------------
__global__ void cumsumA_kernel() {
    int c = blockIdx.x * 256 + threadIdx.x;
    int b = blockIdx.y, s = blockIdx.z;
    const float* src = g_kvr  + ((size_t)(b * NT + s * TSEG)) * NC + c;
    float*       dst = g_sumk + ((size_t)(b * NT + s * TSEG)) * NC + c;
    float acc = 0.f;
    for (int t0 = 0; t0 < TSEG; t0 += 16) {
        float buf[16];
#pragma unroll
        for (int j = 0; j < 16; j++) buf[j] = src[(size_t)(t0 + j) * NC];
#pragma unroll
        for (int j = 0; j < 16; j++) { acc += buf[j]; dst[(size_t)(t0 + j) * NC] = acc; }
    }
    g_segtot[(b * NSEG + s) * NC + c] = acc;
}

// ---------------- cumsum phase B: exclusive scan of segment totals ------------
__global__ void segscan_kernel() {
    int c = blockIdx.x * 256 + threadIdx.x;
    int b = blockIdx.y;
    float s = 0.f;
#pragma unroll
    for (int seg = 0; seg < NSEG; seg++) {
        g_segoff[(b * NSEG + seg) * NC + c] = s;
        s += g_segtot[(b * NSEG + seg) * NC + c];
    }
}

// ---------------- rwkv = sigmoid(r)*wkv/(local+offset), then split ------------
__global__ void rwkv_split_kernel() {
    int i = blockIdx.x * 256 + threadIdx.x;       // over NM*KH
    int j = i * 2;
    int row = i >> 9;
    int t = row & (NT - 1);
    int b = row >> 10;
    int c = (i & (KH - 1)) * 2;
    int so = (b * NSEG + (t >> 7)) * NC + c;
    const float* rr = g_kvr + 2 * (size_t)NM * NC;
    float r0 = rr[j], r1 = rr[j + 1];
    float s0 = g_sumk[j]     + g_segoff[so];
    float s1 = g_sumk[j + 1] + g_segoff[so + 1];
    float a = (1.f / (1.f + expf(-r0))) * g_wkv[j]     / s0;
    float bq = (1.f / (1.f + expf(-r1))) * g_wkv[j + 1] / s1;
    split2(a, bq, g_Ah[i], g_Al[i]);
}

// ---------------- kv^T split ----------------------------------------------------
__global__ void kvt_split_kernel() {
    __shared__ float skv[64][65];
    int ut = blockIdx.x;
    int bh = blockIdx.y;
    int b = bh >> 4, h = bh & 15;
    int tid = threadIdx.x;
    int u0 = ut * 64;
    const float* kb = g_kvr + ((size_t)(b * NT + u0)) * NC + h * 64;
    const float* vb = g_kvr + (size_t)NM * NC + ((size_t)(b * NT + u0)) * NC + h * 64;
#pragma unroll
    for (int rr = 0; rr < 16; rr++) {
        int i = tid + rr * 256;
        int uu = i >> 6, c = i & 63;
        skv[uu][c] = kb[(size_t)uu * NC + c] * vb[(size_t)uu * NC + c];
    }
    __syncthreads();
    uint32_t* oh = g_kvTh + (size_t)bh * 64 * KH + ut * 32;
    uint32_t* ol = g_kvTl + (size_t)bh * 64 * KH + ut * 32;
#pragma unroll
    for (int rr = 0; rr < 8; rr++) {
        int j = tid + rr * 256;
        int c = j >> 5, g = j & 31;
        uint32_t hi, lo;
        split2(skv[g * 2][c], skv[g * 2 + 1][c], hi, lo);
        oh[(size_t)c * KH + g] = hi;
        ol[(size_t)c * KH + g] = lo;
    }
}

// ---------------- wkv via tensor cores (bf16x3, causal) ------------------------
#define WR 20
#define WST (64*WR)

__global__ void __launch_bounds__(256) wkv_mma_kernel(const float* __restrict__ beta) {
    __shared__ uint32_t smw[2 * 4 * WST];
    int tt = blockIdx.x, bh = blockIdx.y;
    int b = bh >> 4, h = bh & 15;
    int t0 = tt * 64;
    int tid = threadIdx.x;
    int lrow = tid >> 2, lq = (tid & 3) * 4;

    const uint32_t* pWh = g_WWh + ((size_t)h * NT + t0 + lrow) * KH + lq;
    const uint32_t* pWl = g_WWl + ((size_t)h * NT + t0 + lrow) * KH + lq;
    const uint32_t* pKh = g_kvTh + ((size_t)bh * 64 + lrow) * KH + lq;
    const uint32_t* pKl = g_kvTl + ((size_t)bh * 64 + lrow) * KH + lq;
    uint32_t sb = (uint32_t)__cvta_generic_to_shared(smw) + (lrow * WR + lq) * 4;

    int lane = tid & 31, warp = tid >> 5;
    int wm = (warp >> 1) * 16, wn = (warp & 1) * 32;
    int r = lane >> 2, cc = lane & 3;

    float acc[4][4];
#pragma unroll
    for (int i = 0; i < 4; i++)
#pragma unroll
        for (int j = 0; j < 4; j++) acc[i][j] = 0.f;

    int nut = 2 * (tt + 1);

    cpa16(sb,               pWh);
    cpa16(sb + WST * 4,     pWl);
    cpa16(sb + 2 * WST * 4, pKh);
    cpa16(sb + 3 * WST * 4, pKl);
    CP_COMMIT();

    for (int ut = 0; ut < nut; ut++) {
        if (ut) __syncthreads();
        if (ut + 1 < nut) {
            uint32_t d = sb + ((ut + 1) & 1) * 4 * WST * 4;
            int o = (ut + 1) * 16;
            cpa16(d,               pWh + o);
            cpa16(d + WST * 4,     pWl + o);
            cpa16(d + 2 * WST * 4, pKh + o);
            cpa16(d + 3 * WST * 4, pKl + o);
            CP_COMMIT();
            asm volatile("cp.async.wait_group 1;");
        } else {
            asm volatile("cp.async.wait_group 0;");
        }
        __syncthreads();

        const uint32_t* S   = smw + (ut & 1) * 4 * WST;
        const uint32_t* SWh = S;
        const uint32_t* SWl = S + WST;
        const uint32_t* SKh = S + 2 * WST;
        const uint32_t* SKl = S + 3 * WST;
#pragma unroll
        for (int ks = 0; ks < 2; ks++) {
            int rb = (wm + r) * WR + ks * 8;
            uint32_t ah[4], al[4];
            ah[0] = SWh[rb + cc];          ah[1] = SWh[rb + 8 * WR + cc];
            ah[2] = SWh[rb + cc + 4];      ah[3] = SWh[rb + 8 * WR + cc + 4];
            al[0] = SWl[rb + cc];          al[1] = SWl[rb + 8 * WR + cc];
            al[2] = SWl[rb + cc + 4];      al[3] = SWl[rb + 8 * WR + cc + 4];
#pragma unroll
            for (int nj = 0; nj < 4; nj++) {
                int nb = (wn + nj * 8 + r) * WR + ks * 8;
                uint32_t bh0 = SKh[nb + cc], bh1 = SKh[nb + cc + 4];
                uint32_t bl0 = SKl[nb + cc], bl1 = SKl[nb + cc + 4];
                mma_bf16(acc[nj], ah, bh0, bh1);
                mma_bf16(acc[nj], al, bh0, bh1);
                mma_bf16(acc[nj], ah, bl0, bl1);
            }
        }
    }

    int tlo = t0 + wm + r, thi = tlo + 8;
    float be_lo = beta[h * NT + tlo], be_hi = beta[h * NT + thi];
    float* orow_lo = g_wkv + ((size_t)(b * NT + tlo)) * NC + h * 64;
    float* orow_hi = g_wkv + ((size_t)(b * NT + thi)) * NC + h * 64;
#pragma unroll
    for (int nj = 0; nj < 4; nj++) {
        int col = wn + nj * 8 + cc * 2;
        float2 o1 = {acc[nj][0] * be_lo, acc[nj][1] * be_lo};
        float2 o2 = {acc[nj][2] * be_hi, acc[nj][3] * be_hi};
        *(float2*)&orow_lo[col] = o1;
        *(float2*)&orow_hi[col] = o2;
    }
}

// ---------------- bf16x3 GEMM, K-tile 32, fused k/v/r or output ---------------
// MODE 0: grid (64,24); sel=by>>3 picks {Wk,Wv,Wr}; exp epilogue for sel==0.
// MODE 1: grid (64,8); weight slab 3 (Wo); bias bo; *gamma[t] epilogue.
#define RS 20                  // row stride in u32 (16 data + 4 pad)
#define WS (128*RS)            // u32 per array per stage

template<int MODE>
__global__ void __launch_bounds__(256, 2) gemm_bf16x3_k32(
    const uint32_t* __restrict__ Ah, const uint32_t* __restrict__ Al,
    float* __restrict__ Cout,
    const float* __restrict__ b0p, const float* __restrict__ b1p,
    const float* __restrict__ b2p, const float* __restrict__ gamma)
{
    extern __shared__ uint32_t sm[];
    uint32_t* SAh = sm;                // [2][WS]
    uint32_t* SAl = sm + 2 * WS;
    uint32_t* SBh = sm + 4 * WS;
    uint32_t* SBl = sm + 6 * WS;

    int tid = threadIdx.x;
    int m0 = blockIdx.x * 128;
    int sel, n0;
    const float* bias;
    float* C;
    if (MODE == 0) {
        sel = blockIdx.y >> 3;
        n0 = (blockIdx.y & 7) * 128;
        bias = (sel == 0) ? b0p : (sel == 1) ? b1p : b2p;
        C = Cout + (size_t)sel * NM * NC;
    } else {
        sel = 3;
        n0 = blockIdx.y * 128;
        bias = b0p;
        C = Cout;
    }
    const uint32_t* Bh = g_Wh + (size_t)sel * NC * KH;
    const uint32_t* Bl = g_Wl + (size_t)sel * NC * KH;

    int lrow = tid >> 1;
    int lg = (tid & 1) * 8;
    const uint32_t* pAh = Ah + (size_t)(m0 + lrow) * KH + lg;
    const uint32_t* pAl = Al + (size_t)(m0 + lrow) * KH + lg;
    const uint32_t* pBh = Bh + (size_t)(n0 + lrow) * KH + lg;
    const uint32_t* pBl = Bl + (size_t)(n0 + lrow) * KH + lg;
    uint32_t sbase = (uint32_t)__cvta_generic_to_shared(sm) + (lrow * RS + lg) * 4;

    int lane = tid & 31, warp = tid >> 5;
    int wm = (warp >> 1) * 32, wn = (warp & 1) * 64;
    int r = lane >> 2, cc = lane & 3;

    float acc[2][8][4];
#pragma unroll
    for (int a = 0; a < 2; a++)
#pragma unroll
        for (int b = 0; b < 8; b++)
#pragma unroll
            for (int q = 0; q < 4; q++) acc[a][b][q] = 0.f;

    {
        uint32_t d = sbase;
        cpa16(d,              pAh);      cpa16(d + 16,              pAh + 4);
        cpa16(d + 2*WS*4,     pAl);      cpa16(d + 2*WS*4 + 16,     pAl + 4);
        cpa16(d + 4*WS*4,     pBh);      cpa16(d + 4*WS*4 + 16,     pBh + 4);
        cpa16(d + 6*WS*4,     pBl);      cpa16(d + 6*WS*4 + 16,     pBl + 4);
        CP_COMMIT();
    }

    for (int kt = 0; kt < 32; kt++) {
        if (kt) __syncthreads();
        if (kt + 1 < 32) {
            uint32_t d = sbase + ((kt + 1) & 1) * WS * 4;
            int o = (kt + 1) * 16;
            cpa16(d,              pAh + o);  cpa16(d + 16,              pAh + o + 4);
            cpa16(d + 2*WS*4,     pAl + o);  cpa16(d + 2*WS*4 + 16,     pAl + o + 4);
            cpa16(d + 4*WS*4,     pBh + o);  cpa16(d + 4*WS*4 + 16,     pBh + o + 4);
            cpa16(d + 6*WS*4,     pBl + o);  cpa16(d + 6*WS*4 + 16,     pBl + o + 4);
            CP_COMMIT();
            asm volatile("cp.async.wait_group 1;");
        } else {
            asm volatile("cp.async.wait_group 0;");
        }
        __syncthreads();

        int st = (kt & 1) * WS;
#pragma unroll
        for (int ks = 0; ks < 2; ks++) {
            uint32_t ah[2][4], al[2][4];
#pragma unroll
            for (int mi = 0; mi < 2; mi++) {
                int rb  = st + (wm + mi * 16 + r) * RS + ks * 8;
                int rb8 = rb + 8 * RS;
                ah[mi][0] = SAh[rb + cc];     ah[mi][1] = SAh[rb8 + cc];
                ah[mi][2] = SAh[rb + cc + 4]; ah[mi][3] = SAh[rb8 + cc + 4];
                al[mi][0] = SAl[rb + cc];     al[mi][1] = SAl[rb8 + cc];
                al[mi][2] = SAl[rb + cc + 4]; al[mi][3] = SAl[rb8 + cc + 4];
            }
#pragma unroll
            for (int nj = 0; nj < 8; nj++) {
                int nb = st + (wn + nj * 8 + r) * RS + ks * 8;
                uint32_t bh0 = SBh[nb + cc], bh1 = SBh[nb + cc + 4];
                uint32_t bl0 = SBl[nb + cc], bl1 = SBl[nb + cc + 4];
#pragma unroll
                for (int mi = 0; mi < 2; mi++) {
                    mma_bf16(acc[mi][nj], ah[mi], bh0, bh1);
                    mma_bf16(acc[mi][nj], al[mi], bh0, bh1);
                    mma_bf16(acc[mi][nj], ah[mi], bl0, bl1);
                }
            }
        }
    }

#pragma unroll
    for (int mi = 0; mi < 2; mi++) {
        int mlo = m0 + wm + mi * 16 + r;
        int mhi = mlo + 8;
        float glo = 1.f, ghi = 1.f;
        if (MODE == 1) { glo = gamma[mlo & (NT - 1)]; ghi = gamma[mhi & (NT - 1)]; }
#pragma unroll
        for (int nj = 0; nj < 8; nj++) {
            int col = n0 + wn + nj * 8 + cc * 2;
            float b0 = bias[col], b1 = bias[col + 1];
            float v0 = acc[mi][nj][0] + b0, v1 = acc[mi][nj][1] + b1;
            float v2 = acc[mi][nj][2] + b0, v3 = acc[mi][nj][3] + b1;
            if (MODE == 0) {
                if (sel == 0) {
                    v0 = expf(fminf(fmaxf(v0, -60.f), 30.f));
                    v1 = expf(fminf(fmaxf(v1, -60.f), 30.f));
                    v2 = expf(fminf(fmaxf(v2, -60.f), 30.f));
                    v3 = expf(fminf(fmaxf(v3, -60.f), 30.f));
                }
            } else {
                v0 *= glo; v1 *= glo; v2 *= ghi; v3 *= ghi;
            }
            float2 o01 = {v0, v1}, o23 = {v2, v3};
            *(float2*)&C[(size_t)mlo * NC + col] = o01;
            *(float2*)&C[(size_t)mhi * NC + col] = o23;
        }
    }
}

// ---------------- host launch -------------------------------------------------
extern "C" void kernel_launch(void* const* d_in, const int* in_sizes, int n_in,
                              void* d_out, int out_size) {
    (void)in_sizes; (void)n_in; (void)out_size;
    const float* x      = (const float*)d_in[0];
    const float* time_w = (const float*)d_in[1];
    const float* alpha  = (const float*)d_in[2];
    const float* beta   = (const float*)d_in[3];
    const float* gamma  = (const float*)d_in[4];
    const float* Wk = (const float*)d_in[5];
    const float* bk = (const float*)d_in[6];
    const float* Wv = (const float*)d_in[7];
    const float* bv = (const float*)d_in[8];
    const float* Wr = (const float*)d_in[9];
    const float* br = (const float*)d_in[10];
    const float* Wo = (const float*)d_in[11];
    const float* bo = (const float*)d_in[12];
    float* out = (float*)d_out;

    float *kvr;
    uint32_t *Ah, *Al;
    cudaGetSymbolAddress((void**)&kvr, g_kvr);
    cudaGetSymbolAddress((void**)&Ah,  g_Ah);
    cudaGetSymbolAddress((void**)&Al,  g_Al);

    size_t smem = 8 * WS * 4;   // 80KB
    static int attr_set = 0;
    if (!attr_set) {
        cudaFuncSetAttribute(gemm_bf16x3_k32<0>,
                             cudaFuncAttributeMaxDynamicSharedMemorySize, (int)smem);
        cudaFuncSetAttribute(gemm_bf16x3_k32<1>,
                             cudaFuncAttributeMaxDynamicSharedMemorySize, (int)smem);
        attr_set = 1;
    }

    split_w_all_kernel<<<4 * NC * KH / 256, 256>>>(Wk, Wv, Wr, Wo);
    build_W_kernel<<<NH * NT * KH / 256, 256>>>(time_w, alpha);
    build_xs_split_kernel<<<NM * KH / 256, 256>>>(x);

    gemm_bf16x3_k32<0><<<dim3(NM / 128, 24), 256, smem>>>(Ah, Al, kvr, bk, bv, br, nullptr);

    cumsumA_kernel<<<dim3(NC / 256, NB, NSEG), 256>>>();
    segscan_kernel<<<dim3(NC / 256, NB), 256>>>();

    kvt_split_kernel<<<dim3(NT / 64, NB * NH), 256>>>();
    wkv_mma_kernel<<<dim3(NT / 64, NB * NH), 256>>>(beta);

    rwkv_split_kernel<<<NM * KH / 256, 256>>>();

    gemm_bf16x3_k32<1><<<dim3(NM / 128, 8), 256, smem>>>(Ah, Al, out, bo, nullptr, nullptr, gamma);
}

// round 6
// speedup vs baseline: 2.4063x; 1.0735x over previous
#include <cuda_runtime.h>
#include <cuda_bf16.h>
#include <math.h>
#include <stdint.h>

#define NB 8
#define NT 1024
#define NC 1024
#define NH 16
#define NM (NB*NT)
#define KH 512            // K/2 (bf16 pairs packed along K)
#define NSEG 8
#define TSEG (NT/NSEG)

// ---------------- scratch (static device globals, no allocation) -------------
__device__ float    g_kvr [3*NM*NC];      // k, v, r
__device__ float    g_sumk[NM*NC];        // per-segment local cumsum
__device__ float    g_segtot[NB*NSEG*NC];
__device__ float    g_segoff[NB*NSEG*NC];
__device__ float    g_wkv [NM*NC];
__device__ uint32_t g_Ah  [NM*KH];        // packed bf16x2 hi of current A operand
__device__ uint32_t g_Al  [NM*KH];        // packed bf16x2 lo
__device__ uint32_t g_Wh  [4*NC*KH];      // Wk,Wv,Wr,Wo hi splits (contiguous)
__device__ uint32_t g_Wl  [4*NC*KH];
__device__ uint32_t g_WWh [NH*NT*KH];     // decay matrix W[h][t][u] hi
__device__ uint32_t g_WWl [NH*NT*KH];
__device__ uint32_t g_kvTh[NB*NH*64*KH];  // kv^T [bh][c][u-pairs] hi
__device__ uint32_t g_kvTl[NB*NH*64*KH];

// ---------------- helpers -----------------------------------------------------
__device__ __forceinline__ void split2(float a, float b, uint32_t& hi, uint32_t& lo) {
    float fa = __bfloat162float(__float2bfloat16(a));
    float fb = __bfloat162float(__float2bfloat16(b));
    float la = a - fa, lb = b - fb;
    asm("cvt.rn.bf16x2.f32 %0, %1, %2;" : "=r"(hi) : "f"(fb), "f"(fa));
    asm("cvt.rn.bf16x2.f32 %0, %1, %2;" : "=r"(lo) : "f"(lb), "f"(la));
}

__device__ __forceinline__ void mma_bf16(float* c, const uint32_t* a,
                                         uint32_t b0, uint32_t b1) {
    asm volatile(
        "mma.sync.aligned.m16n8k16.row.col.f32.bf16.bf16.f32 "
        "{%0,%1,%2,%3},{%4,%5,%6,%7},{%8,%9},{%0,%1,%2,%3};"
        : "+f"(c[0]), "+f"(c[1]), "+f"(c[2]), "+f"(c[3])
        : "r"(a[0]), "r"(a[1]), "r"(a[2]), "r"(a[3]), "r"(b0), "r"(b1));
}

__device__ __forceinline__ void ldm_x4(uint32_t* r, uint32_t addr) {
    asm volatile("ldmatrix.sync.aligned.m8n8.x4.shared.b16 {%0,%1,%2,%3}, [%4];"
                 : "=r"(r[0]), "=r"(r[1]), "=r"(r[2]), "=r"(r[3]) : "r"(addr));
}

__device__ __forceinline__ void cpa16(uint32_t d, const void* s) {
    asm volatile("cp.async.cg.shared.global [%0], [%1], 16;" :: "r"(d), "l"(s));
}
#define CP_COMMIT() asm volatile("cp.async.commit_group;")

// ---------------- weight split: all 4 weights in one launch -------------------
__global__ void split_w_all_kernel(const float* __restrict__ W0,
                                   const float* __restrict__ W1,
                                   const float* __restrict__ W2,
                                   const float* __restrict__ W3) {
    int i = blockIdx.x * 256 + threadIdx.x;       // over 4*NC*KH
    int w = i >> 19;                              // NC*KH = 512K
    int j = i & (NC * KH - 1);
    const float* W = (w == 0) ? W0 : (w == 1) ? W1 : (w == 2) ? W2 : W3;
    float2 v = ((const float2*)W)[j];
    split2(v.x, v.y, g_Wh[i], g_Wl[i]);
}

// ---------------- decay matrix precompute --------------------------------------
__global__ void build_W_kernel(const float* __restrict__ tw,
                               const float* __restrict__ alpha) {
    int i = blockIdx.x * 256 + threadIdx.x;       // over NH*NT*KH
    int u = (i & (KH - 1)) * 2;
    int t = (i >> 9) & (NT - 1);
    int h = i >> 19;
    float w0 = 0.f, w1 = 0.f;
    if (u <= t)     w0 = tw[h * NT + 1023 - t + u]     * alpha[h * NT + u];
    if (u + 1 <= t) w1 = tw[h * NT + 1023 - t + u + 1] * alpha[h * NT + u + 1];
    split2(w0, w1, g_WWh[i], g_WWl[i]);
}

// ---------------- time-shift + split ------------------------------------------
__global__ void build_xs_split_kernel(const float* __restrict__ x) {
    int i = blockIdx.x * 256 + threadIdx.x;       // over NM*KH
    int kk2 = i & (KH - 1);
    int row = i >> 9;
    int t = row & (NT - 1);
    int c = kk2 * 2;
    float a = 0.f, b = 0.f;
    if (c < NC / 2) {
        if (t != 0) {
            float2 v = *(const float2*)(x + (size_t)(row - 1) * NC + c);
            a = v.x; b = v.y;
        }
    } else {
        float2 v = *(const float2*)(x + (size_t)row * NC + c);
        a = v.x; b = v.y;
    }
    split2(a, b, g_Ah[i], g_Al[i]);
}

// ---------------- cumsum phase A: per-segment local scans ---------------------
__global__ void cumsumA_kernel() {
    int c = blockIdx.x * 256 + threadIdx.x;
    int b = blockIdx.y, s = blockIdx.z;
    const float* src = g_kvr  + ((size_t)(b * NT + s * TSEG)) * NC + c;
    float*       dst = g_sumk + ((size_t)(b * NT + s * TSEG)) * NC + c;
    float acc = 0.f;
    for (int t0 = 0; t0 < TSEG; t0 += 16) {
        float buf[16];
#pragma unroll
        for (int j = 0; j < 16; j++) buf[j] = src[(size_t)(t0 + j) * NC];
#pragma unroll
        for (int j = 0; j < 16; j++) { acc += buf[j]; dst[(size_t)(t0 + j) * NC] = acc; }
    }
    g_segtot[(b * NSEG + s) * NC + c] = acc;
}

// ---------------- cumsum phase B: exclusive scan of segment totals ------------
__global__ void segscan_kernel() {
    int c = blockIdx.x * 256 + threadIdx.x;
    int b = blockIdx.y;
    float s = 0.f;
#pragma unroll
    for (int seg = 0; seg < NSEG; seg++) {
        g_segoff[(b * NSEG + seg) * NC + c] = s;
        s += g_segtot[(b * NSEG + seg) * NC + c];
    }
}

// ---------------- rwkv = sigmoid(r)*wkv/(local+offset), then split ------------
__global__ void rwkv_split_kernel() {
    int i = blockIdx.x * 256 + threadIdx.x;       // over NM*KH
    int j = i * 2;
    int row = i >> 9;
    int t = row & (NT - 1);
    int b = row >> 10;
    int c = (i & (KH - 1)) * 2;
    int so = (b * NSEG + (t >> 7)) * NC + c;
    const float* rr = g_kvr + 2 * (size_t)NM * NC;
    float r0 = rr[j], r1 = rr[j + 1];
    float s0 = g_sumk[j]     + g_segoff[so];
    float s1 = g_sumk[j + 1] + g_segoff[so + 1];
    float a = (1.f / (1.f + expf(-r0))) * g_wkv[j]     / s0;
    float bq = (1.f / (1.f + expf(-r1))) * g_wkv[j + 1] / s1;
    split2(a, bq, g_Ah[i], g_Al[i]);
}

// ---------------- kv^T split ----------------------------------------------------
__global__ void kvt_split_kernel() {
    __shared__ float skv[64][65];
    int ut = blockIdx.x;
    int bh = blockIdx.y;
    int b = bh >> 4, h = bh & 15;
    int tid = threadIdx.x;
    int u0 = ut * 64;
    const float* kb = g_kvr + ((size_t)(b * NT + u0)) * NC + h * 64;
    const float* vb = g_kvr + (size_t)NM * NC + ((size_t)(b * NT + u0)) * NC + h * 64;
#pragma unroll
    for (int rr = 0; rr < 16; rr++) {
        int i = tid + rr * 256;
        int uu = i >> 6, c = i & 63;
        skv[uu][c] = kb[(size_t)uu * NC + c] * vb[(size_t)uu * NC + c];
    }
    __syncthreads();
    uint32_t* oh = g_kvTh + (size_t)bh * 64 * KH + ut * 32;
    uint32_t* ol = g_kvTl + (size_t)bh * 64 * KH + ut * 32;
#pragma unroll
    for (int rr = 0; rr < 8; rr++) {
        int j = tid + rr * 256;
        int c = j >> 5, g = j & 31;
        uint32_t hi, lo;
        split2(skv[g * 2][c], skv[g * 2 + 1][c], hi, lo);
        oh[(size_t)c * KH + g] = hi;
        ol[(size_t)c * KH + g] = lo;
    }
}

// ---------------- wkv via tensor cores (bf16x3, causal, ldmatrix) --------------
#define WR 20
#define WST (64*WR)

__global__ void __launch_bounds__(256) wkv_mma_kernel(const float* __restrict__ beta) {
    __shared__ uint32_t smw[2 * 4 * WST];
    int tt = blockIdx.x, bh = blockIdx.y;
    int b = bh >> 4, h = bh & 15;
    int t0 = tt * 64;
    int tid = threadIdx.x;
    int lrow = tid >> 2, lq = (tid & 3) * 4;

    const uint32_t* pWh = g_WWh + ((size_t)h * NT + t0 + lrow) * KH + lq;
    const uint32_t* pWl = g_WWl + ((size_t)h * NT + t0 + lrow) * KH + lq;
    const uint32_t* pKh = g_kvTh + ((size_t)bh * 64 + lrow) * KH + lq;
    const uint32_t* pKl = g_kvTl + ((size_t)bh * 64 + lrow) * KH + lq;
    uint32_t smw_b = (uint32_t)__cvta_generic_to_shared(smw);
    uint32_t sb = smw_b + (lrow * WR + lq) * 4;

    int lane = tid & 31, warp = tid >> 5;
    int wm = (warp >> 1) * 16, wn = (warp & 1) * 32;
    int r = lane >> 2, cc = lane & 3;

    // ldmatrix per-lane bases (u32 units)
    int a_base = (wm + (lane & 15)) * WR + (lane >> 4) * 4;
    int b_base = (wn + ((lane >> 4) << 3) + (lane & 7)) * WR + ((lane >> 3) & 1) * 4;

    float acc[4][4];
#pragma unroll
    for (int i = 0; i < 4; i++)
#pragma unroll
        for (int j = 0; j < 4; j++) acc[i][j] = 0.f;

    int nut = 2 * (tt + 1);

    cpa16(sb,               pWh);
    cpa16(sb + WST * 4,     pWl);
    cpa16(sb + 2 * WST * 4, pKh);
    cpa16(sb + 3 * WST * 4, pKl);
    CP_COMMIT();

    for (int ut = 0; ut < nut; ut++) {
        if (ut) __syncthreads();
        if (ut + 1 < nut) {
            uint32_t d = sb + ((ut + 1) & 1) * 4 * WST * 4;
            int o = (ut + 1) * 16;
            cpa16(d,               pWh + o);
            cpa16(d + WST * 4,     pWl + o);
            cpa16(d + 2 * WST * 4, pKh + o);
            cpa16(d + 3 * WST * 4, pKl + o);
            CP_COMMIT();
            asm volatile("cp.async.wait_group 1;");
        } else {
            asm volatile("cp.async.wait_group 0;");
        }
        __syncthreads();

        uint32_t stoff = (ut & 1) * 4 * WST;
#pragma unroll
        for (int ks = 0; ks < 2; ks++) {
            uint32_t ah[4], al[4];
            uint32_t ai = smw_b + (stoff + a_base + ks * 8) * 4;
            ldm_x4(ah, ai);
            ldm_x4(al, ai + WST * 4);
#pragma unroll
            for (int jp = 0; jp < 2; jp++) {
                uint32_t bhf[4], blf[4];
                uint32_t bi = smw_b + (stoff + b_base + jp * 16 * WR + ks * 8) * 4;
                ldm_x4(bhf, bi + 2 * WST * 4);
                ldm_x4(blf, bi + 3 * WST * 4);
#pragma unroll
                for (int hf = 0; hf < 2; hf++) {
                    float* a4 = acc[jp * 2 + hf];
                    mma_bf16(a4, ah, bhf[hf * 2], bhf[hf * 2 + 1]);
                    mma_bf16(a4, al, bhf[hf * 2], bhf[hf * 2 + 1]);
                    mma_bf16(a4, ah, blf[hf * 2], blf[hf * 2 + 1]);
                }
            }
        }
    }

    int tlo = t0 + wm + r, thi = tlo + 8;
    float be_lo = beta[h * NT + tlo], be_hi = beta[h * NT + thi];
    float* orow_lo = g_wkv + ((size_t)(b * NT + tlo)) * NC + h * 64;
    float* orow_hi = g_wkv + ((size_t)(b * NT + thi)) * NC + h * 64;
#pragma unroll
    for (int nj = 0; nj < 4; nj++) {
        int col = wn + nj * 8 + cc * 2;
        float2 o1 = {acc[nj][0] * be_lo, acc[nj][1] * be_lo};
        float2 o2 = {acc[nj][2] * be_hi, acc[nj][3] * be_hi};
        *(float2*)&orow_lo[col] = o1;
        *(float2*)&orow_hi[col] = o2;
    }
}

// ---------------- bf16x3 GEMM, K-tile 32, ldmatrix fragments ------------------
// MODE 0: grid (64,24); sel=by>>3 picks {Wk,Wv,Wr}; exp epilogue for sel==0.
// MODE 1: grid (64,8); weight slab 3 (Wo); bias bo; *gamma[t] epilogue.
#define RS 20                  // row stride in u32 (16 data + 4 pad)
#define WS (128*RS)            // u32 per array per stage

template<int MODE>
__global__ void __launch_bounds__(256, 2) gemm_bf16x3_k32(
    const uint32_t* __restrict__ Ah, const uint32_t* __restrict__ Al,
    float* __restrict__ Cout,
    const float* __restrict__ b0p, const float* __restrict__ b1p,
    const float* __restrict__ b2p, const float* __restrict__ gamma)
{
    extern __shared__ uint32_t sm[];
    int tid = threadIdx.x;
    int m0 = blockIdx.x * 128;
    int sel, n0;
    const float* bias;
    float* C;
    if (MODE == 0) {
        sel = blockIdx.y >> 3;
        n0 = (blockIdx.y & 7) * 128;
        bias = (sel == 0) ? b0p : (sel == 1) ? b1p : b2p;
        C = Cout + (size_t)sel * NM * NC;
    } else {
        sel = 3;
        n0 = blockIdx.y * 128;
        bias = b0p;
        C = Cout;
    }
    const uint32_t* Bh = g_Wh + (size_t)sel * NC * KH;
    const uint32_t* Bl = g_Wl + (size_t)sel * NC * KH;

    int lrow = tid >> 1;
    int lg = (tid & 1) * 8;
    const uint32_t* pAh = Ah + (size_t)(m0 + lrow) * KH + lg;
    const uint32_t* pAl = Al + (size_t)(m0 + lrow) * KH + lg;
    const uint32_t* pBh = Bh + (size_t)(n0 + lrow) * KH + lg;
    const uint32_t* pBl = Bl + (size_t)(n0 + lrow) * KH + lg;
    uint32_t smem_b = (uint32_t)__cvta_generic_to_shared(sm);
    uint32_t sbase = smem_b + (lrow * RS + lg) * 4;

    int lane = tid & 31, warp = tid >> 5;
    int wm = (warp >> 1) * 32, wn = (warp & 1) * 64;
    int r = lane >> 2, cc = lane & 3;

    // ldmatrix per-lane bases (u32 units)
    int a_base = (wm + (lane & 15)) * RS + (lane >> 4) * 4;
    int b_base = (wn + ((lane >> 4) << 3) + (lane & 7)) * RS + ((lane >> 3) & 1) * 4;

    float acc[2][8][4];
#pragma unroll
    for (int a = 0; a < 2; a++)
#pragma unroll
        for (int b = 0; b < 8; b++)
#pragma unroll
            for (int q = 0; q < 4; q++) acc[a][b][q] = 0.f;

    {
        uint32_t d = sbase;
        cpa16(d,              pAh);      cpa16(d + 16,              pAh + 4);
        cpa16(d + 2*WS*4,     pAl);      cpa16(d + 2*WS*4 + 16,     pAl + 4);
        cpa16(d + 4*WS*4,     pBh);      cpa16(d + 4*WS*4 + 16,     pBh + 4);
        cpa16(d + 6*WS*4,     pBl);      cpa16(d + 6*WS*4 + 16,     pBl + 4);
        CP_COMMIT();
    }

    for (int kt = 0; kt < 32; kt++) {
        if (kt) __syncthreads();
        if (kt + 1 < 32) {
            uint32_t d = sbase + ((kt + 1) & 1) * WS * 4;
            int o = (kt + 1) * 16;
            cpa16(d,              pAh + o);  cpa16(d + 16,              pAh + o + 4);
            cpa16(d + 2*WS*4,     pAl + o);  cpa16(d + 2*WS*4 + 16,     pAl + o + 4);
            cpa16(d + 4*WS*4,     pBh + o);  cpa16(d + 4*WS*4 + 16,     pBh + o + 4);
            cpa16(d + 6*WS*4,     pBl + o);  cpa16(d + 6*WS*4 + 16,     pBl + o + 4);
            CP_COMMIT();
            asm volatile("cp.async.wait_group 1;");
        } else {
            asm volatile("cp.async.wait_group 0;");
        }
        __syncthreads();

        uint32_t st = (kt & 1) * WS;
#pragma unroll
        for (int ks = 0; ks < 2; ks++) {
            uint32_t ah[2][4], al[2][4];
#pragma unroll
            for (int mi = 0; mi < 2; mi++) {
                uint32_t ai = smem_b + (st + a_base + mi * 16 * RS + ks * 8) * 4;
                ldm_x4(ah[mi], ai);
                ldm_x4(al[mi], ai + 2 * WS * 4);
            }
#pragma unroll
            for (int jp = 0; jp < 4; jp++) {
                uint32_t bhf[4], blf[4];
                uint32_t bi = smem_b + (st + b_base + jp * 16 * RS + ks * 8) * 4;
                ldm_x4(bhf, bi + 4 * WS * 4);
                ldm_x4(blf, bi + 6 * WS * 4);
#pragma unroll
                for (int hf = 0; hf < 2; hf++) {
#pragma unroll
                    for (int mi = 0; mi < 2; mi++) {
                        float* a4 = acc[mi][jp * 2 + hf];
                        mma_bf16(a4, ah[mi], bhf[hf * 2], bhf[hf * 2 + 1]);
                        mma_bf16(a4, al[mi], bhf[hf * 2], bhf[hf * 2 + 1]);
                        mma_bf16(a4, ah[mi], blf[hf * 2], blf[hf * 2 + 1]);
                    }
                }
            }
        }
    }

#pragma unroll
    for (int mi = 0; mi < 2; mi++) {
        int mlo = m0 + wm + mi * 16 + r;
        int mhi = mlo + 8;
        float glo = 1.f, ghi = 1.f;
        if (MODE == 1) { glo = gamma[mlo & (NT - 1)]; ghi = gamma[mhi & (NT - 1)]; }
#pragma unroll
        for (int nj = 0; nj < 8; nj++) {
            int col = n0 + wn + nj * 8 + cc * 2;
            float b0 = bias[col], b1 = bias[col + 1];
            float v0 = acc[mi][nj][0] + b0, v1 = acc[mi][nj][1] + b1;
            float v2 = acc[mi][nj][2] + b0, v3 = acc[mi][nj][3] + b1;
            if (MODE == 0) {
                if (sel == 0) {
                    v0 = expf(fminf(fmaxf(v0, -60.f), 30.f));
                    v1 = expf(fminf(fmaxf(v1, -60.f), 30.f));
                    v2 = expf(fminf(fmaxf(v2, -60.f), 30.f));
                    v3 = expf(fminf(fmaxf(v3, -60.f), 30.f));
                }
            } else {
                v0 *= glo; v1 *= glo; v2 *= ghi; v3 *= ghi;
            }
            float2 o01 = {v0, v1}, o23 = {v2, v3};
            *(float2*)&C[(size_t)mlo * NC + col] = o01;
            *(float2*)&C[(size_t)mhi * NC + col] = o23;
        }
    }
}

// ---------------- host launch -------------------------------------------------
extern "C" void kernel_launch(void* const* d_in, const int* in_sizes, int n_in,
                              void* d_out, int out_size) {
    (void)in_sizes; (void)n_in; (void)out_size;
    const float* x      = (const float*)d_in[0];
    const float* time_w = (const float*)d_in[1];
    const float* alpha  = (const float*)d_in[2];
    const float* beta   = (const float*)d_in[3];
    const float* gamma  = (const float*)d_in[4];
    const float* Wk = (const float*)d_in[5];
    const float* bk = (const float*)d_in[6];
    const float* Wv = (const float*)d_in[7];
    const float* bv = (const float*)d_in[8];
    const float* Wr = (const float*)d_in[9];
    const float* br = (const float*)d_in[10];
    const float* Wo = (const float*)d_in[11];
    const float* bo = (const float*)d_in[12];
    float* out = (float*)d_out;

    float *kvr;
    uint32_t *Ah, *Al;
    cudaGetSymbolAddress((void**)&kvr, g_kvr);
    cudaGetSymbolAddress((void**)&Ah,  g_Ah);
    cudaGetSymbolAddress((void**)&Al,  g_Al);

    size_t smem = 8 * WS * 4;   // 80KB
    static int attr_set = 0;
    if (!attr_set) {
        cudaFuncSetAttribute(gemm_bf16x3_k32<0>,
                             cudaFuncAttributeMaxDynamicSharedMemorySize, (int)smem);
        cudaFuncSetAttribute(gemm_bf16x3_k32<1>,
                             cudaFuncAttributeMaxDynamicSharedMemorySize, (int)smem);
        attr_set = 1;
    }

    split_w_all_kernel<<<4 * NC * KH / 256, 256>>>(Wk, Wv, Wr, Wo);
    build_W_kernel<<<NH * NT * KH / 256, 256>>>(time_w, alpha);
    build_xs_split_kernel<<<NM * KH / 256, 256>>>(x);

    gemm_bf16x3_k32<0><<<dim3(NM / 128, 24), 256, smem>>>(Ah, Al, kvr, bk, bv, br, nullptr);

    cumsumA_kernel<<<dim3(NC / 256, NB, NSEG), 256>>>();
    segscan_kernel<<<dim3(NC / 256, NB), 256>>>();

    kvt_split_kernel<<<dim3(NT / 64, NB * NH), 256>>>();
    wkv_mma_kernel<<<dim3(NT / 64, NB * NH), 256>>>(beta);

    rwkv_split_kernel<<<NM * KH / 256, 256>>>();

    gemm_bf16x3_k32<1><<<dim3(NM / 128, 8), 256, smem>>>(Ah, Al, out, bo, nullptr, nullptr, gamma);
}

// round 7
// speedup vs baseline: 2.4490x; 1.0177x over previous
#include <cuda_runtime.h>
#include <cuda_bf16.h>
#include <math.h>
#include <stdint.h>

#define NB 8
#define NT 1024
#define NC 1024
#define NH 16
#define NM (NB*NT)
#define KH 512            // K/2 (bf16 pairs packed along K)
#define NSEG 8
#define TSEG (NT/NSEG)

// ---------------- scratch (static device globals, no allocation) -------------
__device__ float    g_kvr [3*NM*NC];      // k, v, r
__device__ float    g_sumk[NM*NC];        // per-segment local cumsum
__device__ float    g_segtot[NB*NSEG*NC];
__device__ float    g_segoff[NB*NSEG*NC];
__device__ float    g_wkv [NM*NC];
__device__ uint32_t g_Ah  [NM*KH];        // packed bf16x2 hi of current A operand
__device__ uint32_t g_Al  [NM*KH];        // packed bf16x2 lo
__device__ uint32_t g_Wh  [4*NC*KH];      // Wk,Wv,Wr,Wo hi splits (contiguous)
__device__ uint32_t g_Wl  [4*NC*KH];
__device__ uint32_t g_WWh [NH*NT*KH];     // decay matrix W[h][t][u] hi
__device__ uint32_t g_WWl [NH*NT*KH];
__device__ uint32_t g_kvTh[NB*NH*64*KH];  // kv^T [bh][c][u-pairs] hi
__device__ uint32_t g_kvTl[NB*NH*64*KH];

// ---------------- helpers -----------------------------------------------------
__device__ __forceinline__ void split2(float a, float b, uint32_t& hi, uint32_t& lo) {
    float fa = __bfloat162float(__float2bfloat16(a));
    float fb = __bfloat162float(__float2bfloat16(b));
    float la = a - fa, lb = b - fb;
    asm("cvt.rn.bf16x2.f32 %0, %1, %2;" : "=r"(hi) : "f"(fb), "f"(fa));
    asm("cvt.rn.bf16x2.f32 %0, %1, %2;" : "=r"(lo) : "f"(lb), "f"(la));
}

__device__ __forceinline__ void mma_bf16(float* c, const uint32_t* a,
                                         uint32_t b0, uint32_t b1) {
    asm volatile(
        "mma.sync.aligned.m16n8k16.row.col.f32.bf16.bf16.f32 "
        "{%0,%1,%2,%3},{%4,%5,%6,%7},{%8,%9},{%0,%1,%2,%3};"
        : "+f"(c[0]), "+f"(c[1]), "+f"(c[2]), "+f"(c[3])
        : "r"(a[0]), "r"(a[1]), "r"(a[2]), "r"(a[3]), "r"(b0), "r"(b1));
}

__device__ __forceinline__ void ldm_x4(uint32_t* r, uint32_t addr) {
    asm volatile("ldmatrix.sync.aligned.m8n8.x4.shared.b16 {%0,%1,%2,%3}, [%4];"
                 : "=r"(r[0]), "=r"(r[1]), "=r"(r[2]), "=r"(r[3]) : "r"(addr));
}

__device__ __forceinline__ void cpa16(uint32_t d, const void* s) {
    asm volatile("cp.async.cg.shared.global [%0], [%1], 16;" :: "r"(d), "l"(s));
}
#define CP_COMMIT() asm volatile("cp.async.commit_group;")

// ---------------- weight split: all 4 weights in one launch -------------------
__global__ void split_w_all_kernel(const float* __restrict__ W0,
                                   const float* __restrict__ W1,
                                   const float* __restrict__ W2,
                                   const float* __restrict__ W3) {
    int i = blockIdx.x * 256 + threadIdx.x;       // over 4*NC*KH
    int w = i >> 19;                              // NC*KH = 512K
    int j = i & (NC * KH - 1);
    const float* W = (w == 0) ? W0 : (w == 1) ? W1 : (w == 2) ? W2 : W3;
    float2 v = ((const float2*)W)[j];
    split2(v.x, v.y, g_Wh[i], g_Wl[i]);
}

// ---------------- decay matrix precompute --------------------------------------
__global__ void build_W_kernel(const float* __restrict__ tw,
                               const float* __restrict__ alpha) {
    int i = blockIdx.x * 256 + threadIdx.x;       // over NH*NT*KH
    int u = (i & (KH - 1)) * 2;
    int t = (i >> 9) & (NT - 1);
    int h = i >> 19;
    float w0 = 0.f, w1 = 0.f;
    if (u <= t)     w0 = tw[h * NT + 1023 - t + u]     * alpha[h * NT + u];
    if (u + 1 <= t) w1 = tw[h * NT + 1023 - t + u + 1] * alpha[h * NT + u + 1];
    split2(w0, w1, g_WWh[i], g_WWl[i]);
}

// ---------------- time-shift + split ------------------------------------------
__global__ void build_xs_split_kernel(const float* __restrict__ x) {
    int i = blockIdx.x * 256 + threadIdx.x;       // over NM*KH
    int kk2 = i & (KH - 1);
    int row = i >> 9;
    int t = row & (NT - 1);
    int c = kk2 * 2;
    float a = 0.f, b = 0.f;
    if (c < NC / 2) {
        if (t != 0) {
            float2 v = *(const float2*)(x + (size_t)(row - 1) * NC + c);
            a = v.x; b = v.y;
        }
    } else {
        float2 v = *(const float2*)(x + (size_t)row * NC + c);
        a = v.x; b = v.y;
    }
    split2(a, b, g_Ah[i], g_Al[i]);
}

// ---------------- cumsum phase A: per-segment local scans ---------------------
__global__ void cumsumA_kernel() {
    int c = blockIdx.x * 256 + threadIdx.x;
    int b = blockIdx.y, s = blockIdx.z;
    const float* src = g_kvr  + ((size_t)(b * NT + s * TSEG)) * NC + c;
    float*       dst = g_sumk + ((size_t)(b * NT + s * TSEG)) * NC + c;
    float acc = 0.f;
    for (int t0 = 0; t0 < TSEG; t0 += 16) {
        float buf[16];
#pragma unroll
        for (int j = 0; j < 16; j++) buf[j] = src[(size_t)(t0 + j) * NC];
#pragma unroll
        for (int j = 0; j < 16; j++) { acc += buf[j]; dst[(size_t)(t0 + j) * NC] = acc; }
    }
    g_segtot[(b * NSEG + s) * NC + c] = acc;
}

// ---------------- cumsum phase B: exclusive scan of segment totals ------------
__global__ void segscan_kernel() {
    int c = blockIdx.x * 256 + threadIdx.x;
    int b = blockIdx.y;
    float s = 0.f;
#pragma unroll
    for (int seg = 0; seg < NSEG; seg++) {
        g_segoff[(b * NSEG + seg) * NC + c] = s;
        s += g_segtot[(b * NSEG + seg) * NC + c];
    }
}

// ---------------- rwkv = sigmoid(r)*wkv/(local+offset), then split ------------
__global__ void rwkv_split_kernel() {
    int i = blockIdx.x * 256 + threadIdx.x;       // over NM*KH
    int j = i * 2;
    int row = i >> 9;
    int t = row & (NT - 1);
    int b = row >> 10;
    int c = (i & (KH - 1)) * 2;
    int so = (b * NSEG + (t >> 7)) * NC + c;
    const float* rr = g_kvr + 2 * (size_t)NM * NC;
    float r0 = rr[j], r1 = rr[j + 1];
    float s0 = g_sumk[j]     + g_segoff[so];
    float s1 = g_sumk[j + 1] + g_segoff[so + 1];
    float a = (1.f / (1.f + expf(-r0))) * g_wkv[j]     / s0;
    float bq = (1.f / (1.f + expf(-r1))) * g_wkv[j + 1] / s1;
    split2(a, bq, g_Ah[i], g_Al[i]);
}

// ---------------- kv^T split ----------------------------------------------------
__global__ void kvt_split_kernel() {
    __shared__ float skv[64][65];
    int ut = blockIdx.x;
    int bh = blockIdx.y;
    int b = bh >> 4, h = bh & 15;
    int tid = threadIdx.x;
    int u0 = ut * 64;
    const float* kb = g_kvr + ((size_t)(b * NT + u0)) * NC + h * 64;
    const float* vb = g_kvr + (size_t)NM * NC + ((size_t)(b * NT + u0)) * NC + h * 64;
#pragma unroll
    for (int rr = 0; rr < 16; rr++) {
        int i = tid + rr * 256;
        int uu = i >> 6, c = i & 63;
        skv[uu][c] = kb[(size_t)uu * NC + c] * vb[(size_t)uu * NC + c];
    }
    __syncthreads();
    uint32_t* oh = g_kvTh + (size_t)bh * 64 * KH + ut * 32;
    uint32_t* ol = g_kvTl + (size_t)bh * 64 * KH + ut * 32;
#pragma unroll
    for (int rr = 0; rr < 8; rr++) {
        int j = tid + rr * 256;
        int c = j >> 5, g = j & 31;
        uint32_t hi, lo;
        split2(skv[g * 2][c], skv[g * 2 + 1][c], hi, lo);
        oh[(size_t)c * KH + g] = hi;
        ol[(size_t)c * KH + g] = lo;
    }
}

// ---------------- wkv via tensor cores (bf16x3, causal, ldmatrix) --------------
#define WR 20
#define WST (64*WR)

__global__ void __launch_bounds__(256) wkv_mma_kernel(const float* __restrict__ beta) {
    __shared__ uint32_t smw[2 * 4 * WST];
    int tt = blockIdx.x, bh = blockIdx.y;
    int b = bh >> 4, h = bh & 15;
    int t0 = tt * 64;
    int tid = threadIdx.x;
    int lrow = tid >> 2, lq = (tid & 3) * 4;

    const uint32_t* pWh = g_WWh + ((size_t)h * NT + t0 + lrow) * KH + lq;
    const uint32_t* pWl = g_WWl + ((size_t)h * NT + t0 + lrow) * KH + lq;
    const uint32_t* pKh = g_kvTh + ((size_t)bh * 64 + lrow) * KH + lq;
    const uint32_t* pKl = g_kvTl + ((size_t)bh * 64 + lrow) * KH + lq;
    uint32_t smw_b = (uint32_t)__cvta_generic_to_shared(smw);
    uint32_t sb = smw_b + (lrow * WR + lq) * 4;

    int lane = tid & 31, warp = tid >> 5;
    int wm = (warp >> 1) * 16, wn = (warp & 1) * 32;
    int r = lane >> 2, cc = lane & 3;

    // ldmatrix per-lane bases (u32 units)
    int a_base = (wm + (lane & 15)) * WR + (lane >> 4) * 4;
    int b_base = (wn + ((lane >> 4) << 3) + (lane & 7)) * WR + ((lane >> 3) & 1) * 4;

    float acc[4][4];
#pragma unroll
    for (int i = 0; i < 4; i++)
#pragma unroll
        for (int j = 0; j < 4; j++) acc[i][j] = 0.f;

    int nut = 2 * (tt + 1);

    cpa16(sb,               pWh);
    cpa16(sb + WST * 4,     pWl);
    cpa16(sb + 2 * WST * 4, pKh);
    cpa16(sb + 3 * WST * 4, pKl);
    CP_COMMIT();

    for (int ut = 0; ut < nut; ut++) {
        if (ut) __syncthreads();
        if (ut + 1 < nut) {
            uint32_t d = sb + ((ut + 1) & 1) * 4 * WST * 4;
            int o = (ut + 1) * 16;
            cpa16(d,               pWh + o);
            cpa16(d + WST * 4,     pWl + o);
            cpa16(d + 2 * WST * 4, pKh + o);
            cpa16(d + 3 * WST * 4, pKl + o);
            CP_COMMIT();
            asm volatile("cp.async.wait_group 1;");
        } else {
            asm volatile("cp.async.wait_group 0;");
        }
        __syncthreads();

        uint32_t stoff = (ut & 1) * 4 * WST;
#pragma unroll
        for (int ks = 0; ks < 2; ks++) {
            uint32_t ah[4], al[4];
            uint32_t ai = smw_b + (stoff + a_base + ks * 8) * 4;
            ldm_x4(ah, ai);
            ldm_x4(al, ai + WST * 4);

            uint32_t bhf[2][4], blf[2][4];
#pragma unroll
            for (int jp = 0; jp < 2; jp++) {
                uint32_t bi = smw_b + (stoff + b_base + jp * 16 * WR + ks * 8) * 4;
                ldm_x4(bhf[jp], bi + 2 * WST * 4);
                ldm_x4(blf[jp], bi + 3 * WST * 4);
            }
            // term-major: break acc dependency chains
#pragma unroll
            for (int jp = 0; jp < 2; jp++)
#pragma unroll
                for (int hf = 0; hf < 2; hf++)
                    mma_bf16(acc[jp * 2 + hf], ah, bhf[jp][hf * 2], bhf[jp][hf * 2 + 1]);
#pragma unroll
            for (int jp = 0; jp < 2; jp++)
#pragma unroll
                for (int hf = 0; hf < 2; hf++)
                    mma_bf16(acc[jp * 2 + hf], al, bhf[jp][hf * 2], bhf[jp][hf * 2 + 1]);
#pragma unroll
            for (int jp = 0; jp < 2; jp++)
#pragma unroll
                for (int hf = 0; hf < 2; hf++)
                    mma_bf16(acc[jp * 2 + hf], ah, blf[jp][hf * 2], blf[jp][hf * 2 + 1]);
        }
    }

    int tlo = t0 + wm + r, thi = tlo + 8;
    float be_lo = beta[h * NT + tlo], be_hi = beta[h * NT + thi];
    float* orow_lo = g_wkv + ((size_t)(b * NT + tlo)) * NC + h * 64;
    float* orow_hi = g_wkv + ((size_t)(b * NT + thi)) * NC + h * 64;
#pragma unroll
    for (int nj = 0; nj < 4; nj++) {
        int col = wn + nj * 8 + cc * 2;
        float2 o1 = {acc[nj][0] * be_lo, acc[nj][1] * be_lo};
        float2 o2 = {acc[nj][2] * be_hi, acc[nj][3] * be_hi};
        *(float2*)&orow_lo[col] = o1;
        *(float2*)&orow_hi[col] = o2;
    }
}

// ---------------- bf16x3 GEMM, K-tile 32, ldmatrix + term-major MMA -----------
// MODE 0: grid (64,24); sel=by>>3 picks {Wk,Wv,Wr}; exp epilogue for sel==0.
// MODE 1: grid (64,8); weight slab 3 (Wo); bias bo; *gamma[t] epilogue.
#define RS 20                  // row stride in u32 (16 data + 4 pad)
#define WS (128*RS)            // u32 per array per stage

template<int MODE>
__global__ void __launch_bounds__(256, 2) gemm_bf16x3_k32(
    const uint32_t* __restrict__ Ah, const uint32_t* __restrict__ Al,
    float* __restrict__ Cout,
    const float* __restrict__ b0p, const float* __restrict__ b1p,
    const float* __restrict__ b2p, const float* __restrict__ gamma)
{
    extern __shared__ uint32_t sm[];
    int tid = threadIdx.x;
    int m0 = blockIdx.x * 128;
    int sel, n0;
    const float* bias;
    float* C;
    if (MODE == 0) {
        sel = blockIdx.y >> 3;
        n0 = (blockIdx.y & 7) * 128;
        bias = (sel == 0) ? b0p : (sel == 1) ? b1p : b2p;
        C = Cout + (size_t)sel * NM * NC;
    } else {
        sel = 3;
        n0 = blockIdx.y * 128;
        bias = b0p;
        C = Cout;
    }
    const uint32_t* Bh = g_Wh + (size_t)sel * NC * KH;
    const uint32_t* Bl = g_Wl + (size_t)sel * NC * KH;

    int lrow = tid >> 1;
    int lg = (tid & 1) * 8;
    const uint32_t* pAh = Ah + (size_t)(m0 + lrow) * KH + lg;
    const uint32_t* pAl = Al + (size_t)(m0 + lrow) * KH + lg;
    const uint32_t* pBh = Bh + (size_t)(n0 + lrow) * KH + lg;
    const uint32_t* pBl = Bl + (size_t)(n0 + lrow) * KH + lg;
    uint32_t smem_b = (uint32_t)__cvta_generic_to_shared(sm);
    uint32_t sbase = smem_b + (lrow * RS + lg) * 4;

    int lane = tid & 31, warp = tid >> 5;
    int wm = (warp >> 1) * 32, wn = (warp & 1) * 64;
    int r = lane >> 2, cc = lane & 3;

    // ldmatrix per-lane bases (u32 units)
    int a_base = (wm + (lane & 15)) * RS + (lane >> 4) * 4;
    int b_base = (wn + ((lane >> 4) << 3) + (lane & 7)) * RS + ((lane >> 3) & 1) * 4;

    float acc[2][8][4];
#pragma unroll
    for (int a = 0; a < 2; a++)
#pragma unroll
        for (int b = 0; b < 8; b++)
#pragma unroll
            for (int q = 0; q < 4; q++) acc[a][b][q] = 0.f;

    {
        uint32_t d = sbase;
        cpa16(d,              pAh);      cpa16(d + 16,              pAh + 4);
        cpa16(d + 2*WS*4,     pAl);      cpa16(d + 2*WS*4 + 16,     pAl + 4);
        cpa16(d + 4*WS*4,     pBh);      cpa16(d + 4*WS*4 + 16,     pBh + 4);
        cpa16(d + 6*WS*4,     pBl);      cpa16(d + 6*WS*4 + 16,     pBl + 4);
        CP_COMMIT();
    }

    for (int kt = 0; kt < 32; kt++) {
        if (kt) __syncthreads();
        if (kt + 1 < 32) {
            uint32_t d = sbase + ((kt + 1) & 1) * WS * 4;
            int o = (kt + 1) * 16;
            cpa16(d,              pAh + o);  cpa16(d + 16,              pAh + o + 4);
            cpa16(d + 2*WS*4,     pAl + o);  cpa16(d + 2*WS*4 + 16,     pAl + o + 4);
            cpa16(d + 4*WS*4,     pBh + o);  cpa16(d + 4*WS*4 + 16,     pBh + o + 4);
            cpa16(d + 6*WS*4,     pBl + o);  cpa16(d + 6*WS*4 + 16,     pBl + o + 4);
            CP_COMMIT();
            asm volatile("cp.async.wait_group 1;");
        } else {
            asm volatile("cp.async.wait_group 0;");
        }
        __syncthreads();

        uint32_t st = (kt & 1) * WS;
#pragma unroll
        for (int ks = 0; ks < 2; ks++) {
            uint32_t ah[2][4], al[2][4];
#pragma unroll
            for (int mi = 0; mi < 2; mi++) {
                uint32_t ai = smem_b + (st + a_base + mi * 16 * RS + ks * 8) * 4;
                ldm_x4(ah[mi], ai);
                ldm_x4(al[mi], ai + 2 * WS * 4);
            }
            // process jp in pairs; term-major within pair to break acc chains
#pragma unroll
            for (int jpp = 0; jpp < 2; jpp++) {
                uint32_t bhf[2][4], blf[2][4];
#pragma unroll
                for (int q = 0; q < 2; q++) {
                    int jp = jpp * 2 + q;
                    uint32_t bi = smem_b + (st + b_base + jp * 16 * RS + ks * 8) * 4;
                    ldm_x4(bhf[q], bi + 4 * WS * 4);
                    ldm_x4(blf[q], bi + 6 * WS * 4);
                }
                // term hh (8 accs)
#pragma unroll
                for (int q = 0; q < 2; q++)
#pragma unroll
                    for (int hf = 0; hf < 2; hf++)
#pragma unroll
                        for (int mi = 0; mi < 2; mi++)
                            mma_bf16(acc[mi][(jpp * 2 + q) * 2 + hf], ah[mi],
                                     bhf[q][hf * 2], bhf[q][hf * 2 + 1]);
                // term lh
#pragma unroll
                for (int q = 0; q < 2; q++)
#pragma unroll
                    for (int hf = 0; hf < 2; hf++)
#pragma unroll
                        for (int mi = 0; mi < 2; mi++)
                            mma_bf16(acc[mi][(jpp * 2 + q) * 2 + hf], al[mi],
                                     bhf[q][hf * 2], bhf[q][hf * 2 + 1]);
                // term hl
#pragma unroll
                for (int q = 0; q < 2; q++)
#pragma unroll
                    for (int hf = 0; hf < 2; hf++)
#pragma unroll
                        for (int mi = 0; mi < 2; mi++)
                            mma_bf16(acc[mi][(jpp * 2 + q) * 2 + hf], ah[mi],
                                     blf[q][hf * 2], blf[q][hf * 2 + 1]);
            }
        }
    }

#pragma unroll
    for (int mi = 0; mi < 2; mi++) {
        int mlo = m0 + wm + mi * 16 + r;
        int mhi = mlo + 8;
        float glo = 1.f, ghi = 1.f;
        if (MODE == 1) { glo = gamma[mlo & (NT - 1)]; ghi = gamma[mhi & (NT - 1)]; }
#pragma unroll
        for (int nj = 0; nj < 8; nj++) {
            int col = n0 + wn + nj * 8 + cc * 2;
            float b0 = bias[col], b1 = bias[col + 1];
            float v0 = acc[mi][nj][0] + b0, v1 = acc[mi][nj][1] + b1;
            float v2 = acc[mi][nj][2] + b0, v3 = acc[mi][nj][3] + b1;
            if (MODE == 0) {
                if (sel == 0) {
                    v0 = expf(fminf(fmaxf(v0, -60.f), 30.f));
                    v1 = expf(fminf(fmaxf(v1, -60.f), 30.f));
                    v2 = expf(fminf(fmaxf(v2, -60.f), 30.f));
                    v3 = expf(fminf(fmaxf(v3, -60.f), 30.f));
                }
            } else {
                v0 *= glo; v1 *= glo; v2 *= ghi; v3 *= ghi;
            }
            float2 o01 = {v0, v1}, o23 = {v2, v3};
            *(float2*)&C[(size_t)mlo * NC + col] = o01;
            *(float2*)&C[(size_t)mhi * NC + col] = o23;
        }
    }
}

// ---------------- host launch -------------------------------------------------
extern "C" void kernel_launch(void* const* d_in, const int* in_sizes, int n_in,
                              void* d_out, int out_size) {
    (void)in_sizes; (void)n_in; (void)out_size;
    const float* x      = (const float*)d_in[0];
    const float* time_w = (const float*)d_in[1];
    const float* alpha  = (const float*)d_in[2];
    const float* beta   = (const float*)d_in[3];
    const float* gamma  = (const float*)d_in[4];
    const float* Wk = (const float*)d_in[5];
    const float* bk = (const float*)d_in[6];
    const float* Wv = (const float*)d_in[7];
    const float* bv = (const float*)d_in[8];
    const float* Wr = (const float*)d_in[9];
    const float* br = (const float*)d_in[10];
    const float* Wo = (const float*)d_in[11];
    const float* bo = (const float*)d_in[12];
    float* out = (float*)d_out;

    float *kvr;
    uint32_t *Ah, *Al;
    cudaGetSymbolAddress((void**)&kvr, g_kvr);
    cudaGetSymbolAddress((void**)&Ah,  g_Ah);
    cudaGetSymbolAddress((void**)&Al,  g_Al);

    size_t smem = 8 * WS * 4;   // 80KB
    static int attr_set = 0;
    if (!attr_set) {
        cudaFuncSetAttribute(gemm_bf16x3_k32<0>,
                             cudaFuncAttributeMaxDynamicSharedMemorySize, (int)smem);
        cudaFuncSetAttribute(gemm_bf16x3_k32<1>,
                             cudaFuncAttributeMaxDynamicSharedMemorySize, (int)smem);
        attr_set = 1;
    }

    split_w_all_kernel<<<4 * NC * KH / 256, 256>>>(Wk, Wv, Wr, Wo);
    build_W_kernel<<<NH * NT * KH / 256, 256>>>(time_w, alpha);
    build_xs_split_kernel<<<NM * KH / 256, 256>>>(x);

    gemm_bf16x3_k32<0><<<dim3(NM / 128, 24), 256, smem>>>(Ah, Al, kvr, bk, bv, br, nullptr);

    cumsumA_kernel<<<dim3(NC / 256, NB, NSEG), 256>>>();
    segscan_kernel<<<dim3(NC / 256, NB), 256>>>();

    kvt_split_kernel<<<dim3(NT / 64, NB * NH), 256>>>();
    wkv_mma_kernel<<<dim3(NT / 64, NB * NH), 256>>>(beta);

    rwkv_split_kernel<<<NM * KH / 256, 256>>>();

    gemm_bf16x3_k32<1><<<dim3(NM / 128, 8), 256, smem>>>(Ah, Al, out, bo, nullptr, nullptr, gamma);
}

// round 8
// speedup vs baseline: 3.2936x; 1.3449x over previous
#include <cuda_runtime.h>
#include <cuda_fp16.h>
#include <math.h>
#include <stdint.h>

#define NB 8
#define NT 1024
#define NC 1024
#define NH 16
#define NM (NB*NT)
#define KH 512            // K/2 (fp16 pairs packed along K)
#define NSEG 8
#define TSEG (NT/NSEG)

// ---------------- scratch (static device globals, no allocation) -------------
__device__ float    g_kvr [3*NM*NC];      // k, v, r
__device__ float    g_sumk[NM*NC];        // per-segment local cumsum
__device__ float    g_segtot[NB*NSEG*NC];
__device__ float    g_segoff[NB*NSEG*NC];
__device__ float    g_wkv [NM*NC];
__device__ uint32_t g_Ah  [NM*KH];        // packed f16x2 hi of current A operand
__device__ uint32_t g_Al  [NM*KH];        // packed f16x2 lo
__device__ uint32_t g_Wh  [4*NC*KH];      // Wk,Wv,Wr,Wo rounded to fp16 (B operand)
__device__ uint32_t g_WWh [NH*NT*KH];     // decay matrix W[h][t][u] hi (A of wkv)
__device__ uint32_t g_WWl [NH*NT*KH];     // decay matrix lo
__device__ uint32_t g_kvTh[NB*NH*64*KH];  // kv^T [bh][c][u-pairs] rounded fp16

// ---------------- helpers -----------------------------------------------------
__device__ __forceinline__ uint32_t pack2h(float a, float b) {
    __half ha = __float2half_rn(a), hb = __float2half_rn(b);
    return (uint32_t)__half_as_ushort(ha) | ((uint32_t)__half_as_ushort(hb) << 16);
}

__device__ __forceinline__ void split2h(float a, float b, uint32_t& hi, uint32_t& lo) {
    __half ha = __float2half_rn(a), hb = __float2half_rn(b);
    float fa = __half2float(ha), fb = __half2float(hb);
    __half la = __float2half_rn(a - fa), lb = __float2half_rn(b - fb);
    hi = (uint32_t)__half_as_ushort(ha) | ((uint32_t)__half_as_ushort(hb) << 16);
    lo = (uint32_t)__half_as_ushort(la) | ((uint32_t)__half_as_ushort(lb) << 16);
}

__device__ __forceinline__ void mma_f16(float* c, const uint32_t* a,
                                        uint32_t b0, uint32_t b1) {
    asm volatile(
        "mma.sync.aligned.m16n8k16.row.col.f32.f16.f16.f32 "
        "{%0,%1,%2,%3},{%4,%5,%6,%7},{%8,%9},{%0,%1,%2,%3};"
        : "+f"(c[0]), "+f"(c[1]), "+f"(c[2]), "+f"(c[3])
        : "r"(a[0]), "r"(a[1]), "r"(a[2]), "r"(a[3]), "r"(b0), "r"(b1));
}

__device__ __forceinline__ void ldm_x4(uint32_t* r, uint32_t addr) {
    asm volatile("ldmatrix.sync.aligned.m8n8.x4.shared.b16 {%0,%1,%2,%3}, [%4];"
                 : "=r"(r[0]), "=r"(r[1]), "=r"(r[2]), "=r"(r[3]) : "r"(addr));
}

__device__ __forceinline__ void cpa16(uint32_t d, const void* s) {
    asm volatile("cp.async.cg.shared.global [%0], [%1], 16;" :: "r"(d), "l"(s));
}
#define CP_COMMIT() asm volatile("cp.async.commit_group;")

// ---------------- weight round: all 4 weights -> fp16 in one launch -----------
__global__ void split_w_all_kernel(const float* __restrict__ W0,
                                   const float* __restrict__ W1,
                                   const float* __restrict__ W2,
                                   const float* __restrict__ W3) {
    int i = blockIdx.x * 256 + threadIdx.x;       // over 4*NC*KH
    int w = i >> 19;                              // NC*KH = 512K
    int j = i & (NC * KH - 1);
    const float* W = (w == 0) ? W0 : (w == 1) ? W1 : (w == 2) ? W2 : W3;
    float2 v = ((const float2*)W)[j];
    g_Wh[i] = pack2h(v.x, v.y);
}

// ---------------- decay matrix precompute (fp16 split) -------------------------
__global__ void build_W_kernel(const float* __restrict__ tw,
                               const float* __restrict__ alpha) {
    int i = blockIdx.x * 256 + threadIdx.x;       // over NH*NT*KH
    int u = (i & (KH - 1)) * 2;
    int t = (i >> 9) & (NT - 1);
    int h = i >> 19;
    float w0 = 0.f, w1 = 0.f;
    if (u <= t)     w0 = tw[h * NT + 1023 - t + u]     * alpha[h * NT + u];
    if (u + 1 <= t) w1 = tw[h * NT + 1023 - t + u + 1] * alpha[h * NT + u + 1];
    split2h(w0, w1, g_WWh[i], g_WWl[i]);
}

// ---------------- time-shift + fp16 split --------------------------------------
__global__ void build_xs_split_kernel(const float* __restrict__ x) {
    int i = blockIdx.x * 256 + threadIdx.x;       // over NM*KH
    int kk2 = i & (KH - 1);
    int row = i >> 9;
    int t = row & (NT - 1);
    int c = kk2 * 2;
    float a = 0.f, b = 0.f;
    if (c < NC / 2) {
        if (t != 0) {
            float2 v = *(const float2*)(x + (size_t)(row - 1) * NC + c);
            a = v.x; b = v.y;
        }
    } else {
        float2 v = *(const float2*)(x + (size_t)row * NC + c);
        a = v.x; b = v.y;
    }
    split2h(a, b, g_Ah[i], g_Al[i]);
}

// ---------------- cumsum phase A: per-segment local scans ---------------------
__global__ void cumsumA_kernel() {
    int c = blockIdx.x * 256 + threadIdx.x;
    int b = blockIdx.y, s = blockIdx.z;
    const float* src = g_kvr  + ((size_t)(b * NT + s * TSEG)) * NC + c;
    float*       dst = g_sumk + ((size_t)(b * NT + s * TSEG)) * NC + c;
    float acc = 0.f;
    for (int t0 = 0; t0 < TSEG; t0 += 16) {
        float buf[16];
#pragma unroll
        for (int j = 0; j < 16; j++) buf[j] = src[(size_t)(t0 + j) * NC];
#pragma unroll
        for (int j = 0; j < 16; j++) { acc += buf[j]; dst[(size_t)(t0 + j) * NC] = acc; }
    }
    g_segtot[(b * NSEG + s) * NC + c] = acc;
}

// ---------------- cumsum phase B: exclusive scan of segment totals ------------
__global__ void segscan_kernel() {
    int c = blockIdx.x * 256 + threadIdx.x;
    int b = blockIdx.y;
    float s = 0.f;
#pragma unroll
    for (int seg = 0; seg < NSEG; seg++) {
        g_segoff[(b * NSEG + seg) * NC + c] = s;
        s += g_segtot[(b * NSEG + seg) * NC + c];
    }
}

// ---------------- rwkv = sigmoid(r)*wkv/(local+offset), then fp16 split -------
__global__ void rwkv_split_kernel() {
    int i = blockIdx.x * 256 + threadIdx.x;       // over NM*KH
    int j = i * 2;
    int row = i >> 9;
    int t = row & (NT - 1);
    int b = row >> 10;
    int c = (i & (KH - 1)) * 2;
    int so = (b * NSEG + (t >> 7)) * NC + c;
    const float* rr = g_kvr + 2 * (size_t)NM * NC;
    float r0 = rr[j], r1 = rr[j + 1];
    float s0 = g_sumk[j]     + g_segoff[so];
    float s1 = g_sumk[j + 1] + g_segoff[so + 1];
    float a = (1.f / (1.f + expf(-r0))) * g_wkv[j]     / s0;
    float bq = (1.f / (1.f + expf(-r1))) * g_wkv[j + 1] / s1;
    split2h(a, bq, g_Ah[i], g_Al[i]);
}

// ---------------- kv^T: round to fp16 (B operand of wkv) ----------------------
__global__ void kvt_split_kernel() {
    __shared__ float skv[64][65];
    int ut = blockIdx.x;
    int bh = blockIdx.y;
    int b = bh >> 4, h = bh & 15;
    int tid = threadIdx.x;
    int u0 = ut * 64;
    const float* kb = g_kvr + ((size_t)(b * NT + u0)) * NC + h * 64;
    const float* vb = g_kvr + (size_t)NM * NC + ((size_t)(b * NT + u0)) * NC + h * 64;
#pragma unroll
    for (int rr = 0; rr < 16; rr++) {
        int i = tid + rr * 256;
        int uu = i >> 6, c = i & 63;
        skv[uu][c] = kb[(size_t)uu * NC + c] * vb[(size_t)uu * NC + c];
    }
    __syncthreads();
    uint32_t* oh = g_kvTh + (size_t)bh * 64 * KH + ut * 32;
#pragma unroll
    for (int rr = 0; rr < 8; rr++) {
        int j = tid + rr * 256;
        int c = j >> 5, g = j & 31;
        oh[(size_t)c * KH + g] = pack2h(skv[g * 2][c], skv[g * 2 + 1][c]);
    }
}

// ---------------- wkv via tensor cores (fp16x2, causal, ldmatrix) --------------
// Regions (2 stages each): [WWh | WWl | Kh]
#define WR 20
#define WST (64*WR)

__global__ void __launch_bounds__(256) wkv_mma_kernel(const float* __restrict__ beta) {
    __shared__ uint32_t smw[6 * WST];
    int tt = blockIdx.x, bh = blockIdx.y;
    int b = bh >> 4, h = bh & 15;
    int t0 = tt * 64;
    int tid = threadIdx.x;
    int lrow = tid >> 2, lq = (tid & 3) * 4;

    const uint32_t* pWh = g_WWh + ((size_t)h * NT + t0 + lrow) * KH + lq;
    const uint32_t* pWl = g_WWl + ((size_t)h * NT + t0 + lrow) * KH + lq;
    const uint32_t* pKh = g_kvTh + ((size_t)bh * 64 + lrow) * KH + lq;
    uint32_t smw_b = (uint32_t)__cvta_generic_to_shared(smw);
    uint32_t sb = smw_b + (lrow * WR + lq) * 4;

    int lane = tid & 31, warp = tid >> 5;
    int wm = (warp >> 1) * 16, wn = (warp & 1) * 32;
    int r = lane >> 2, cc = lane & 3;

    // ldmatrix per-lane bases (u32 units)
    int a_base = (wm + (lane & 15)) * WR + (lane >> 4) * 4;
    int b_base = (wn + ((lane >> 4) << 3) + (lane & 7)) * WR + ((lane >> 3) & 1) * 4;

    float acc[4][4];
#pragma unroll
    for (int i = 0; i < 4; i++)
#pragma unroll
        for (int j = 0; j < 4; j++) acc[i][j] = 0.f;

    int nut = 2 * (tt + 1);

    cpa16(sb,               pWh);
    cpa16(sb + 2 * WST * 4, pWl);
    cpa16(sb + 4 * WST * 4, pKh);
    CP_COMMIT();

    for (int ut = 0; ut < nut; ut++) {
        if (ut) __syncthreads();
        if (ut + 1 < nut) {
            uint32_t d = sb + ((ut + 1) & 1) * WST * 4;
            int o = (ut + 1) * 16;
            cpa16(d,               pWh + o);
            cpa16(d + 2 * WST * 4, pWl + o);
            cpa16(d + 4 * WST * 4, pKh + o);
            CP_COMMIT();
            asm volatile("cp.async.wait_group 1;");
        } else {
            asm volatile("cp.async.wait_group 0;");
        }
        __syncthreads();

        uint32_t stoff = (ut & 1) * WST;
#pragma unroll
        for (int ks = 0; ks < 2; ks++) {
            uint32_t ah[4], al[4];
            uint32_t ai = smw_b + (stoff + a_base + ks * 8) * 4;
            ldm_x4(ah, ai);
            ldm_x4(al, ai + 2 * WST * 4);

            uint32_t bhf[2][4];
#pragma unroll
            for (int jp = 0; jp < 2; jp++) {
                uint32_t bi = smw_b + (stoff + b_base + jp * 16 * WR + ks * 8) * 4;
                ldm_x4(bhf[jp], bi + 4 * WST * 4);
            }
            // term-major: hh then lh
#pragma unroll
            for (int jp = 0; jp < 2; jp++)
#pragma unroll
                for (int hf = 0; hf < 2; hf++)
                    mma_f16(acc[jp * 2 + hf], ah, bhf[jp][hf * 2], bhf[jp][hf * 2 + 1]);
#pragma unroll
            for (int jp = 0; jp < 2; jp++)
#pragma unroll
                for (int hf = 0; hf < 2; hf++)
                    mma_f16(acc[jp * 2 + hf], al, bhf[jp][hf * 2], bhf[jp][hf * 2 + 1]);
        }
    }

    int tlo = t0 + wm + r, thi = tlo + 8;
    float be_lo = beta[h * NT + tlo], be_hi = beta[h * NT + thi];
    float* orow_lo = g_wkv + ((size_t)(b * NT + tlo)) * NC + h * 64;
    float* orow_hi = g_wkv + ((size_t)(b * NT + thi)) * NC + h * 64;
#pragma unroll
    for (int nj = 0; nj < 4; nj++) {
        int col = wn + nj * 8 + cc * 2;
        float2 o1 = {acc[nj][0] * be_lo, acc[nj][1] * be_lo};
        float2 o2 = {acc[nj][2] * be_hi, acc[nj][3] * be_hi};
        *(float2*)&orow_lo[col] = o1;
        *(float2*)&orow_hi[col] = o2;
    }
}

// ---------------- fp16x2 GEMM, K-tile 32, ldmatrix, 3 smem regions ------------
// MODE 0: grid (64,24); sel=by>>3 picks {Wk,Wv,Wr}; exp epilogue for sel==0.
// MODE 1: grid (64,8); weight slab 3 (Wo); bias bo; *gamma[t] epilogue.
#define RS 20                  // row stride in u32 (16 data + 4 pad)
#define WS (128*RS)            // u32 per array per stage

template<int MODE>
__global__ void __launch_bounds__(256, 2) gemm_f16x2_k32(
    const uint32_t* __restrict__ Ah, const uint32_t* __restrict__ Al,
    float* __restrict__ Cout,
    const float* __restrict__ b0p, const float* __restrict__ b1p,
    const float* __restrict__ b2p, const float* __restrict__ gamma)
{
    extern __shared__ uint32_t sm[];
    int tid = threadIdx.x;
    int m0 = blockIdx.x * 128;
    int sel, n0;
    const float* bias;
    float* C;
    if (MODE == 0) {
        sel = blockIdx.y >> 3;
        n0 = (blockIdx.y & 7) * 128;
        bias = (sel == 0) ? b0p : (sel == 1) ? b1p : b2p;
        C = Cout + (size_t)sel * NM * NC;
    } else {
        sel = 3;
        n0 = blockIdx.y * 128;
        bias = b0p;
        C = Cout;
    }
    const uint32_t* Bh = g_Wh + (size_t)sel * NC * KH;

    int lrow = tid >> 1;
    int lg = (tid & 1) * 8;
    const uint32_t* pAh = Ah + (size_t)(m0 + lrow) * KH + lg;
    const uint32_t* pAl = Al + (size_t)(m0 + lrow) * KH + lg;
    const uint32_t* pBh = Bh + (size_t)(n0 + lrow) * KH + lg;
    uint32_t smem_b = (uint32_t)__cvta_generic_to_shared(sm);
    uint32_t sbase = smem_b + (lrow * RS + lg) * 4;

    int lane = tid & 31, warp = tid >> 5;
    int wm = (warp >> 1) * 32, wn = (warp & 1) * 64;
    int r = lane >> 2, cc = lane & 3;

    // ldmatrix per-lane bases (u32 units)
    int a_base = (wm + (lane & 15)) * RS + (lane >> 4) * 4;
    int b_base = (wn + ((lane >> 4) << 3) + (lane & 7)) * RS + ((lane >> 3) & 1) * 4;

    float acc[2][8][4];
#pragma unroll
    for (int a = 0; a < 2; a++)
#pragma unroll
        for (int b = 0; b < 8; b++)
#pragma unroll
            for (int q = 0; q < 4; q++) acc[a][b][q] = 0.f;

    {
        uint32_t d = sbase;
        cpa16(d,              pAh);      cpa16(d + 16,              pAh + 4);
        cpa16(d + 2*WS*4,     pAl);      cpa16(d + 2*WS*4 + 16,     pAl + 4);
        cpa16(d + 4*WS*4,     pBh);      cpa16(d + 4*WS*4 + 16,     pBh + 4);
        CP_COMMIT();
    }

    for (int kt = 0; kt < 32; kt++) {
        if (kt) __syncthreads();
        if (kt + 1 < 32) {
            uint32_t d = sbase + ((kt + 1) & 1) * WS * 4;
            int o = (kt + 1) * 16;
            cpa16(d,              pAh + o);  cpa16(d + 16,              pAh + o + 4);
            cpa16(d + 2*WS*4,     pAl + o);  cpa16(d + 2*WS*4 + 16,     pAl + o + 4);
            cpa16(d + 4*WS*4,     pBh + o);  cpa16(d + 4*WS*4 + 16,     pBh + o + 4);
            CP_COMMIT();
            asm volatile("cp.async.wait_group 1;");
        } else {
            asm volatile("cp.async.wait_group 0;");
        }
        __syncthreads();

        uint32_t st = (kt & 1) * WS;
#pragma unroll
        for (int ks = 0; ks < 2; ks++) {
            uint32_t ah[2][4], al[2][4];
#pragma unroll
            for (int mi = 0; mi < 2; mi++) {
                uint32_t ai = smem_b + (st + a_base + mi * 16 * RS + ks * 8) * 4;
                ldm_x4(ah[mi], ai);
                ldm_x4(al[mi], ai + 2 * WS * 4);
            }
            // process jp in pairs; term-major within pair
#pragma unroll
            for (int jpp = 0; jpp < 2; jpp++) {
                uint32_t bhf[2][4];
#pragma unroll
                for (int q = 0; q < 2; q++) {
                    int jp = jpp * 2 + q;
                    uint32_t bi = smem_b + (st + b_base + jp * 16 * RS + ks * 8) * 4;
                    ldm_x4(bhf[q], bi + 4 * WS * 4);
                }
                // term hh (8 accs)
#pragma unroll
                for (int q = 0; q < 2; q++)
#pragma unroll
                    for (int hf = 0; hf < 2; hf++)
#pragma unroll
                        for (int mi = 0; mi < 2; mi++)
                            mma_f16(acc[mi][(jpp * 2 + q) * 2 + hf], ah[mi],
                                    bhf[q][hf * 2], bhf[q][hf * 2 + 1]);
                // term lh
#pragma unroll
                for (int q = 0; q < 2; q++)
#pragma unroll
                    for (int hf = 0; hf < 2; hf++)
#pragma unroll
                        for (int mi = 0; mi < 2; mi++)
                            mma_f16(acc[mi][(jpp * 2 + q) * 2 + hf], al[mi],
                                    bhf[q][hf * 2], bhf[q][hf * 2 + 1]);
            }
        }
    }

#pragma unroll
    for (int mi = 0; mi < 2; mi++) {
        int mlo = m0 + wm + mi * 16 + r;
        int mhi = mlo + 8;
        float glo = 1.f, ghi = 1.f;
        if (MODE == 1) { glo = gamma[mlo & (NT - 1)]; ghi = gamma[mhi & (NT - 1)]; }
#pragma unroll
        for (int nj = 0; nj < 8; nj++) {
            int col = n0 + wn + nj * 8 + cc * 2;
            float b0 = bias[col], b1 = bias[col + 1];
            float v0 = acc[mi][nj][0] + b0, v1 = acc[mi][nj][1] + b1;
            float v2 = acc[mi][nj][2] + b0, v3 = acc[mi][nj][3] + b1;
            if (MODE == 0) {
                if (sel == 0) {
                    v0 = expf(fminf(fmaxf(v0, -60.f), 30.f));
                    v1 = expf(fminf(fmaxf(v1, -60.f), 30.f));
                    v2 = expf(fminf(fmaxf(v2, -60.f), 30.f));
                    v3 = expf(fminf(fmaxf(v3, -60.f), 30.f));
                }
            } else {
                v0 *= glo; v1 *= glo; v2 *= ghi; v3 *= ghi;
            }
            float2 o01 = {v0, v1}, o23 = {v2, v3};
            *(float2*)&C[(size_t)mlo * NC + col] = o01;
            *(float2*)&C[(size_t)mhi * NC + col] = o23;
        }
    }
}

// ---------------- host launch -------------------------------------------------
extern "C" void kernel_launch(void* const* d_in, const int* in_sizes, int n_in,
                              void* d_out, int out_size) {
    (void)in_sizes; (void)n_in; (void)out_size;
    const float* x      = (const float*)d_in[0];
    const float* time_w = (const float*)d_in[1];
    const float* alpha  = (const float*)d_in[2];
    const float* beta   = (const float*)d_in[3];
    const float* gamma  = (const float*)d_in[4];
    const float* Wk = (const float*)d_in[5];
    const float* bk = (const float*)d_in[6];
    const float* Wv = (const float*)d_in[7];
    const float* bv = (const float*)d_in[8];
    const float* Wr = (const float*)d_in[9];
    const float* br = (const float*)d_in[10];
    const float* Wo = (const float*)d_in[11];
    const float* bo = (const float*)d_in[12];
    float* out = (float*)d_out;

    float *kvr;
    uint32_t *Ah, *Al;
    cudaGetSymbolAddress((void**)&kvr, g_kvr);
    cudaGetSymbolAddress((void**)&Ah,  g_Ah);
    cudaGetSymbolAddress((void**)&Al,  g_Al);

    size_t smem = 6 * WS * 4;   // 60KB (3 regions x 2 stages)
    static int attr_set = 0;
    if (!attr_set) {
        cudaFuncSetAttribute(gemm_f16x2_k32<0>,
                             cudaFuncAttributeMaxDynamicSharedMemorySize, (int)smem);
        cudaFuncSetAttribute(gemm_f16x2_k32<1>,
                             cudaFuncAttributeMaxDynamicSharedMemorySize, (int)smem);
        attr_set = 1;
    }

    split_w_all_kernel<<<4 * NC * KH / 256, 256>>>(Wk, Wv, Wr, Wo);
    build_W_kernel<<<NH * NT * KH / 256, 256>>>(time_w, alpha);
    build_xs_split_kernel<<<NM * KH / 256, 256>>>(x);

    gemm_f16x2_k32<0><<<dim3(NM / 128, 24), 256, smem>>>(Ah, Al, kvr, bk, bv, br, nullptr);

    cumsumA_kernel<<<dim3(NC / 256, NB, NSEG), 256>>>();
    segscan_kernel<<<dim3(NC / 256, NB), 256>>>();

    kvt_split_kernel<<<dim3(NT / 64, NB * NH), 256>>>();
    wkv_mma_kernel<<<dim3(NT / 64, NB * NH), 256>>>(beta);

    rwkv_split_kernel<<<NM * KH / 256, 256>>>();

    gemm_f16x2_k32<1><<<dim3(NM / 128, 8), 256, smem>>>(Ah, Al, out, bo, nullptr, nullptr, gamma);
}

// round 9
// speedup vs baseline: 3.3314x; 1.0115x over previous
#include <cuda_runtime.h>
#include <cuda_fp16.h>
#include <math.h>
#include <stdint.h>

#define NB 8
#define NT 1024
#define NC 1024
#define NH 16
#define NM (NB*NT)
#define KH 512            // K/2 (fp16 pairs packed along K)
#define NSEG 8
#define TSEG (NT/NSEG)

// ---------------- scratch (static device globals, no allocation) -------------
__device__ float    g_kvr [3*NM*NC];      // k, v, r
__device__ float    g_sumk[NM*NC];        // per-segment local cumsum
__device__ float    g_segtot[NB*NSEG*NC];
__device__ float    g_segoff[NB*NSEG*NC];
__device__ float    g_wkv [NM*NC];
__device__ uint32_t g_Ah  [NM*KH];        // packed f16x2 hi of current A operand
__device__ uint32_t g_Al  [NM*KH];        // packed f16x2 lo
__device__ uint32_t g_Wh  [4*NC*KH];      // Wk,Wv,Wr,Wo rounded to fp16 (B operand)
__device__ uint32_t g_WWh [NH*NT*KH];     // decay matrix W[h][t][u] hi (A of wkv)
__device__ uint32_t g_WWl [NH*NT*KH];     // decay matrix lo
__device__ uint32_t g_kvTh[NB*NH*64*KH];  // kv^T [bh][c][u-pairs] rounded fp16

// ---------------- helpers -----------------------------------------------------
__device__ __forceinline__ uint32_t pack2h(float a, float b) {
    __half ha = __float2half_rn(a), hb = __float2half_rn(b);
    return (uint32_t)__half_as_ushort(ha) | ((uint32_t)__half_as_ushort(hb) << 16);
}

__device__ __forceinline__ void split2h(float a, float b, uint32_t& hi, uint32_t& lo) {
    __half ha = __float2half_rn(a), hb = __float2half_rn(b);
    float fa = __half2float(ha), fb = __half2float(hb);
    __half la = __float2half_rn(a - fa), lb = __float2half_rn(b - fb);
    hi = (uint32_t)__half_as_ushort(ha) | ((uint32_t)__half_as_ushort(hb) << 16);
    lo = (uint32_t)__half_as_ushort(la) | ((uint32_t)__half_as_ushort(lb) << 16);
}

__device__ __forceinline__ void mma_f16(float* c, const uint32_t* a,
                                        uint32_t b0, uint32_t b1) {
    asm volatile(
        "mma.sync.aligned.m16n8k16.row.col.f32.f16.f16.f32 "
        "{%0,%1,%2,%3},{%4,%5,%6,%7},{%8,%9},{%0,%1,%2,%3};"
        : "+f"(c[0]), "+f"(c[1]), "+f"(c[2]), "+f"(c[3])
        : "r"(a[0]), "r"(a[1]), "r"(a[2]), "r"(a[3]), "r"(b0), "r"(b1));
}

__device__ __forceinline__ void ldm_x4(uint32_t* r, uint32_t addr) {
    asm volatile("ldmatrix.sync.aligned.m8n8.x4.shared.b16 {%0,%1,%2,%3}, [%4];"
                 : "=r"(r[0]), "=r"(r[1]), "=r"(r[2]), "=r"(r[3]) : "r"(addr));
}

__device__ __forceinline__ void cpa16(uint32_t d, const void* s) {
    asm volatile("cp.async.cg.shared.global [%0], [%1], 16;" :: "r"(d), "l"(s));
}
#define CP_COMMIT() asm volatile("cp.async.commit_group;")
#define CP_WAIT1()  asm volatile("cp.async.wait_group 1;")
#define CP_WAIT0()  asm volatile("cp.async.wait_group 0;")

// ---------------- weight round: all 4 weights -> fp16 in one launch -----------
__global__ void split_w_all_kernel(const float* __restrict__ W0,
                                   const float* __restrict__ W1,
                                   const float* __restrict__ W2,
                                   const float* __restrict__ W3) {
    int i = blockIdx.x * 256 + threadIdx.x;       // over 4*NC*KH
    int w = i >> 19;                              // NC*KH = 512K
    int j = i & (NC * KH - 1);
    const float* W = (w == 0) ? W0 : (w == 1) ? W1 : (w == 2) ? W2 : W3;
    float2 v = ((const float2*)W)[j];
    g_Wh[i] = pack2h(v.x, v.y);
}

// ---------------- decay matrix precompute (fp16 split) -------------------------
__global__ void build_W_kernel(const float* __restrict__ tw,
                               const float* __restrict__ alpha) {
    int i = blockIdx.x * 256 + threadIdx.x;       // over NH*NT*KH
    int u = (i & (KH - 1)) * 2;
    int t = (i >> 9) & (NT - 1);
    int h = i >> 19;
    float w0 = 0.f, w1 = 0.f;
    if (u <= t)     w0 = tw[h * NT + 1023 - t + u]     * alpha[h * NT + u];
    if (u + 1 <= t) w1 = tw[h * NT + 1023 - t + u + 1] * alpha[h * NT + u + 1];
    split2h(w0, w1, g_WWh[i], g_WWl[i]);
}

// ---------------- time-shift + fp16 split --------------------------------------
__global__ void build_xs_split_kernel(const float* __restrict__ x) {
    int i = blockIdx.x * 256 + threadIdx.x;       // over NM*KH
    int kk2 = i & (KH - 1);
    int row = i >> 9;
    int t = row & (NT - 1);
    int c = kk2 * 2;
    float a = 0.f, b = 0.f;
    if (c < NC / 2) {
        if (t != 0) {
            float2 v = *(const float2*)(x + (size_t)(row - 1) * NC + c);
            a = v.x; b = v.y;
        }
    } else {
        float2 v = *(const float2*)(x + (size_t)row * NC + c);
        a = v.x; b = v.y;
    }
    split2h(a, b, g_Ah[i], g_Al[i]);
}

// ---------------- cumsum phase A: per-segment local scans ---------------------
__global__ void cumsumA_kernel() {
    int c = blockIdx.x * 256 + threadIdx.x;
    int b = blockIdx.y, s = blockIdx.z;
    const float* src = g_kvr  + ((size_t)(b * NT + s * TSEG)) * NC + c;
    float*       dst = g_sumk + ((size_t)(b * NT + s * TSEG)) * NC + c;
    float acc = 0.f;
    for (int t0 = 0; t0 < TSEG; t0 += 16) {
        float buf[16];
#pragma unroll
        for (int j = 0; j < 16; j++) buf[j] = src[(size_t)(t0 + j) * NC];
#pragma unroll
        for (int j = 0; j < 16; j++) { acc += buf[j]; dst[(size_t)(t0 + j) * NC] = acc; }
    }
    g_segtot[(b * NSEG + s) * NC + c] = acc;
}

// ---------------- cumsum phase B: exclusive scan of segment totals ------------
__global__ void segscan_kernel() {
    int c = blockIdx.x * 256 + threadIdx.x;
    int b = blockIdx.y;
    float s = 0.f;
#pragma unroll
    for (int seg = 0; seg < NSEG; seg++) {
        g_segoff[(b * NSEG + seg) * NC + c] = s;
        s += g_segtot[(b * NSEG + seg) * NC + c];
    }
}

// ---------------- rwkv = sigmoid(r)*wkv/(local+offset), then fp16 split -------
__global__ void rwkv_split_kernel() {
    int i = blockIdx.x * 256 + threadIdx.x;       // over NM*KH
    int j = i * 2;
    int row = i >> 9;
    int t = row & (NT - 1);
    int b = row >> 10;
    int c = (i & (KH - 1)) * 2;
    int so = (b * NSEG + (t >> 7)) * NC + c;
    const float* rr = g_kvr + 2 * (size_t)NM * NC;
    float r0 = rr[j], r1 = rr[j + 1];
    float s0 = g_sumk[j]     + g_segoff[so];
    float s1 = g_sumk[j + 1] + g_segoff[so + 1];
    float a = (1.f / (1.f + expf(-r0))) * g_wkv[j]     / s0;
    float bq = (1.f / (1.f + expf(-r1))) * g_wkv[j + 1] / s1;
    split2h(a, bq, g_Ah[i], g_Al[i]);
}

// ---------------- kv^T: round to fp16 (B operand of wkv) ----------------------
__global__ void kvt_split_kernel() {
    __shared__ float skv[64][65];
    int ut = blockIdx.x;
    int bh = blockIdx.y;
    int b = bh >> 4, h = bh & 15;
    int tid = threadIdx.x;
    int u0 = ut * 64;
    const float* kb = g_kvr + ((size_t)(b * NT + u0)) * NC + h * 64;
    const float* vb = g_kvr + (size_t)NM * NC + ((size_t)(b * NT + u0)) * NC + h * 64;
#pragma unroll
    for (int rr = 0; rr < 16; rr++) {
        int i = tid + rr * 256;
        int uu = i >> 6, c = i & 63;
        skv[uu][c] = kb[(size_t)uu * NC + c] * vb[(size_t)uu * NC + c];
    }
    __syncthreads();
    uint32_t* oh = g_kvTh + (size_t)bh * 64 * KH + ut * 32;
#pragma unroll
    for (int rr = 0; rr < 8; rr++) {
        int j = tid + rr * 256;
        int c = j >> 5, g = j & 31;
        oh[(size_t)c * KH + g] = pack2h(skv[g * 2][c], skv[g * 2 + 1][c]);
    }
}

// ---------------- wkv via tensor cores (fp16x2, causal, 3-stage pipe) ----------
// Regions (3 stages each): [WWh | WWl | Kh]
#define WR 20
#define WST (64*WR)

__global__ void __launch_bounds__(256) wkv_mma_kernel(const float* __restrict__ beta) {
    __shared__ uint32_t smw[9 * WST];       // 45KB
    int tt = blockIdx.x, bh = blockIdx.y;
    int b = bh >> 4, h = bh & 15;
    int t0 = tt * 64;
    int tid = threadIdx.x;
    int lrow = tid >> 2, lq = (tid & 3) * 4;

    const uint32_t* pWh = g_WWh + ((size_t)h * NT + t0 + lrow) * KH + lq;
    const uint32_t* pWl = g_WWl + ((size_t)h * NT + t0 + lrow) * KH + lq;
    const uint32_t* pKh = g_kvTh + ((size_t)bh * 64 + lrow) * KH + lq;
    uint32_t smw_b = (uint32_t)__cvta_generic_to_shared(smw);
    uint32_t sb = smw_b + (lrow * WR + lq) * 4;

    int lane = tid & 31, warp = tid >> 5;
    int wm = (warp >> 1) * 16, wn = (warp & 1) * 32;
    int r = lane >> 2, cc = lane & 3;

    int a_base = (wm + (lane & 15)) * WR + (lane >> 4) * 4;
    int b_base = (wn + ((lane >> 4) << 3) + (lane & 7)) * WR + ((lane >> 3) & 1) * 4;

    float acc[4][4];
#pragma unroll
    for (int i = 0; i < 4; i++)
#pragma unroll
        for (int j = 0; j < 4; j++) acc[i][j] = 0.f;

    int nut = 2 * (tt + 1);     // >= 2

    // prologue: stages 0 and 1 (slots 0,1)
#pragma unroll
    for (int s = 0; s < 2; s++) {
        uint32_t d = sb + s * WST * 4;
        int o = s * 16;
        cpa16(d,               pWh + o);
        cpa16(d + 3 * WST * 4, pWl + o);
        cpa16(d + 6 * WST * 4, pKh + o);
        CP_COMMIT();
    }

    for (int ut = 0; ut < nut; ut++) {
        if (ut + 1 < nut) CP_WAIT1(); else CP_WAIT0();
        __syncthreads();
        if (ut + 2 < nut) {
            int slot = (ut + 2) % 3;
            uint32_t d = sb + slot * WST * 4;
            int o = (ut + 2) * 16;
            cpa16(d,               pWh + o);
            cpa16(d + 3 * WST * 4, pWl + o);
            cpa16(d + 6 * WST * 4, pKh + o);
            CP_COMMIT();
        }

        uint32_t stoff = (ut % 3) * WST;
#pragma unroll
        for (int ks = 0; ks < 2; ks++) {
            uint32_t ah[4], al[4];
            uint32_t ai = smw_b + (stoff + a_base + ks * 8) * 4;
            ldm_x4(ah, ai);
            ldm_x4(al, ai + 3 * WST * 4);

            uint32_t bhf[2][4];
#pragma unroll
            for (int jp = 0; jp < 2; jp++) {
                uint32_t bi = smw_b + (stoff + b_base + jp * 16 * WR + ks * 8) * 4;
                ldm_x4(bhf[jp], bi + 6 * WST * 4);
            }
#pragma unroll
            for (int jp = 0; jp < 2; jp++)
#pragma unroll
                for (int hf = 0; hf < 2; hf++)
                    mma_f16(acc[jp * 2 + hf], ah, bhf[jp][hf * 2], bhf[jp][hf * 2 + 1]);
#pragma unroll
            for (int jp = 0; jp < 2; jp++)
#pragma unroll
                for (int hf = 0; hf < 2; hf++)
                    mma_f16(acc[jp * 2 + hf], al, bhf[jp][hf * 2], bhf[jp][hf * 2 + 1]);
        }
    }

    int tlo = t0 + wm + r, thi = tlo + 8;
    float be_lo = beta[h * NT + tlo], be_hi = beta[h * NT + thi];
    float* orow_lo = g_wkv + ((size_t)(b * NT + tlo)) * NC + h * 64;
    float* orow_hi = g_wkv + ((size_t)(b * NT + thi)) * NC + h * 64;
#pragma unroll
    for (int nj = 0; nj < 4; nj++) {
        int col = wn + nj * 8 + cc * 2;
        float2 o1 = {acc[nj][0] * be_lo, acc[nj][1] * be_lo};
        float2 o2 = {acc[nj][2] * be_hi, acc[nj][3] * be_hi};
        *(float2*)&orow_lo[col] = o1;
        *(float2*)&orow_hi[col] = o2;
    }
}

// ---------------- fp16x2 GEMM, K-tile 32, 3-stage cp.async pipeline -----------
// MODE 0: grid (64,24); sel=by>>3 picks {Wk,Wv,Wr}; exp epilogue for sel==0.
// MODE 1: grid (64,8); weight slab 3 (Wo); bias bo; *gamma[t] epilogue.
#define RS 20                  // row stride in u32 (16 data + 4 pad)
#define WS (128*RS)            // u32 per region per stage

template<int MODE>
__global__ void __launch_bounds__(256, 2) gemm_f16x2_k32(
    const uint32_t* __restrict__ Ah, const uint32_t* __restrict__ Al,
    float* __restrict__ Cout,
    const float* __restrict__ b0p, const float* __restrict__ b1p,
    const float* __restrict__ b2p, const float* __restrict__ gamma)
{
    extern __shared__ uint32_t sm[];   // [Ah:3][Al:3][Bh:3] stages
    int tid = threadIdx.x;
    int m0 = blockIdx.x * 128;
    int sel, n0;
    const float* bias;
    float* C;
    if (MODE == 0) {
        sel = blockIdx.y >> 3;
        n0 = (blockIdx.y & 7) * 128;
        bias = (sel == 0) ? b0p : (sel == 1) ? b1p : b2p;
        C = Cout + (size_t)sel * NM * NC;
    } else {
        sel = 3;
        n0 = blockIdx.y * 128;
        bias = b0p;
        C = Cout;
    }
    const uint32_t* Bh = g_Wh + (size_t)sel * NC * KH;

    int lrow = tid >> 1;
    int lg = (tid & 1) * 8;
    const uint32_t* pAh = Ah + (size_t)(m0 + lrow) * KH + lg;
    const uint32_t* pAl = Al + (size_t)(m0 + lrow) * KH + lg;
    const uint32_t* pBh = Bh + (size_t)(n0 + lrow) * KH + lg;
    uint32_t smem_b = (uint32_t)__cvta_generic_to_shared(sm);
    uint32_t sbase = smem_b + (lrow * RS + lg) * 4;

    int lane = tid & 31, warp = tid >> 5;
    int wm = (warp >> 1) * 32, wn = (warp & 1) * 64;
    int r = lane >> 2, cc = lane & 3;

    int a_base = (wm + (lane & 15)) * RS + (lane >> 4) * 4;
    int b_base = (wn + ((lane >> 4) << 3) + (lane & 7)) * RS + ((lane >> 3) & 1) * 4;

    float acc[2][8][4];
#pragma unroll
    for (int a = 0; a < 2; a++)
#pragma unroll
        for (int b = 0; b < 8; b++)
#pragma unroll
            for (int q = 0; q < 4; q++) acc[a][b][q] = 0.f;

    // prologue: stages 0, 1
#pragma unroll
    for (int s = 0; s < 2; s++) {
        uint32_t d = sbase + s * WS * 4;
        int o = s * 16;
        cpa16(d,              pAh + o);  cpa16(d + 16,              pAh + o + 4);
        cpa16(d + 3*WS*4,     pAl + o);  cpa16(d + 3*WS*4 + 16,     pAl + o + 4);
        cpa16(d + 6*WS*4,     pBh + o);  cpa16(d + 6*WS*4 + 16,     pBh + o + 4);
        CP_COMMIT();
    }

    for (int kt = 0; kt < 32; kt++) {
        if (kt + 1 < 32) CP_WAIT1(); else CP_WAIT0();
        __syncthreads();
        if (kt + 2 < 32) {
            int slot = (kt + 2) % 3;
            uint32_t d = sbase + slot * WS * 4;
            int o = (kt + 2) * 16;
            cpa16(d,              pAh + o);  cpa16(d + 16,              pAh + o + 4);
            cpa16(d + 3*WS*4,     pAl + o);  cpa16(d + 3*WS*4 + 16,     pAl + o + 4);
            cpa16(d + 6*WS*4,     pBh + o);  cpa16(d + 6*WS*4 + 16,     pBh + o + 4);
            CP_COMMIT();
        }

        uint32_t st = (kt % 3) * WS;
#pragma unroll
        for (int ks = 0; ks < 2; ks++) {
            uint32_t ah[2][4], al[2][4];
#pragma unroll
            for (int mi = 0; mi < 2; mi++) {
                uint32_t ai = smem_b + (st + a_base + mi * 16 * RS + ks * 8) * 4;
                ldm_x4(ah[mi], ai);
                ldm_x4(al[mi], ai + 3 * WS * 4);
            }
#pragma unroll
            for (int jpp = 0; jpp < 2; jpp++) {
                uint32_t bhf[2][4];
#pragma unroll
                for (int q = 0; q < 2; q++) {
                    int jp = jpp * 2 + q;
                    uint32_t bi = smem_b + (st + b_base + jp * 16 * RS + ks * 8) * 4;
                    ldm_x4(bhf[q], bi + 6 * WS * 4);
                }
#pragma unroll
                for (int q = 0; q < 2; q++)
#pragma unroll
                    for (int hf = 0; hf < 2; hf++)
#pragma unroll
                        for (int mi = 0; mi < 2; mi++)
                            mma_f16(acc[mi][(jpp * 2 + q) * 2 + hf], ah[mi],
                                    bhf[q][hf * 2], bhf[q][hf * 2 + 1]);
#pragma unroll
                for (int q = 0; q < 2; q++)
#pragma unroll
                    for (int hf = 0; hf < 2; hf++)
#pragma unroll
                        for (int mi = 0; mi < 2; mi++)
                            mma_f16(acc[mi][(jpp * 2 + q) * 2 + hf], al[mi],
                                    bhf[q][hf * 2], bhf[q][hf * 2 + 1]);
            }
        }
    }

#pragma unroll
    for (int mi = 0; mi < 2; mi++) {
        int mlo = m0 + wm + mi * 16 + r;
        int mhi = mlo + 8;
        float glo = 1.f, ghi = 1.f;
        if (MODE == 1) { glo = gamma[mlo & (NT - 1)]; ghi = gamma[mhi & (NT - 1)]; }
#pragma unroll
        for (int nj = 0; nj < 8; nj++) {
            int col = n0 + wn + nj * 8 + cc * 2;
            float b0 = bias[col], b1 = bias[col + 1];
            float v0 = acc[mi][nj][0] + b0, v1 = acc[mi][nj][1] + b1;
            float v2 = acc[mi][nj][2] + b0, v3 = acc[mi][nj][3] + b1;
            if (MODE == 0) {
                if (sel == 0) {
                    v0 = expf(fminf(fmaxf(v0, -60.f), 30.f));
                    v1 = expf(fminf(fmaxf(v1, -60.f), 30.f));
                    v2 = expf(fminf(fmaxf(v2, -60.f), 30.f));
                    v3 = expf(fminf(fmaxf(v3, -60.f), 30.f));
                }
            } else {
                v0 *= glo; v1 *= glo; v2 *= ghi; v3 *= ghi;
            }
            float2 o01 = {v0, v1}, o23 = {v2, v3};
            *(float2*)&C[(size_t)mlo * NC + col] = o01;
            *(float2*)&C[(size_t)mhi * NC + col] = o23;
        }
    }
}

// ---------------- host launch -------------------------------------------------
extern "C" void kernel_launch(void* const* d_in, const int* in_sizes, int n_in,
                              void* d_out, int out_size) {
    (void)in_sizes; (void)n_in; (void)out_size;
    const float* x      = (const float*)d_in[0];
    const float* time_w = (const float*)d_in[1];
    const float* alpha  = (const float*)d_in[2];
    const float* beta   = (const float*)d_in[3];
    const float* gamma  = (const float*)d_in[4];
    const float* Wk = (const float*)d_in[5];
    const float* bk = (const float*)d_in[6];
    const float* Wv = (const float*)d_in[7];
    const float* bv = (const float*)d_in[8];
    const float* Wr = (const float*)d_in[9];
    const float* br = (const float*)d_in[10];
    const float* Wo = (const float*)d_in[11];
    const float* bo = (const float*)d_in[12];
    float* out = (float*)d_out;

    float *kvr;
    uint32_t *Ah, *Al;
    cudaGetSymbolAddress((void**)&kvr, g_kvr);
    cudaGetSymbolAddress((void**)&Ah,  g_Ah);
    cudaGetSymbolAddress((void**)&Al,  g_Al);

    size_t smem = 9 * WS * 4;   // 90KB (3 regions x 3 stages)
    static int attr_set = 0;
    if (!attr_set) {
        cudaFuncSetAttribute(gemm_f16x2_k32<0>,
                             cudaFuncAttributeMaxDynamicSharedMemorySize, (int)smem);
        cudaFuncSetAttribute(gemm_f16x2_k32<1>,
                             cudaFuncAttributeMaxDynamicSharedMemorySize, (int)smem);
        attr_set = 1;
    }

    split_w_all_kernel<<<4 * NC * KH / 256, 256>>>(Wk, Wv, Wr, Wo);
    build_W_kernel<<<NH * NT * KH / 256, 256>>>(time_w, alpha);
    build_xs_split_kernel<<<NM * KH / 256, 256>>>(x);

    gemm_f16x2_k32<0><<<dim3(NM / 128, 24), 256, smem>>>(Ah, Al, kvr, bk, bv, br, nullptr);

    cumsumA_kernel<<<dim3(NC / 256, NB, NSEG), 256>>>();
    segscan_kernel<<<dim3(NC / 256, NB), 256>>>();

    kvt_split_kernel<<<dim3(NT / 64, NB * NH), 256>>>();
    wkv_mma_kernel<<<dim3(NT / 64, NB * NH), 256>>>(beta);

    rwkv_split_kernel<<<NM * KH / 256, 256>>>();

    gemm_f16x2_k32<1><<<dim3(NM / 128, 8), 256, smem>>>(Ah, Al, out, bo, nullptr, nullptr, gamma);
}